// round 1
// baseline (speedup 1.0000x reference)
#include <cuda_runtime.h>
#include <math.h>
#include <stdint.h>

// Problem constants
#define BB     4
#define PP     65536
#define NPTS   (BB * PP)        // 262144
#define TD     32
#define HID    128
#define NFREQ  6
#define CD     (3 * 2 * NFREQ)  // 36
#define FIN    (TD + CD)        // 68
#define RES    256

// Tile config
#define NP     64               // points per CTA
#define NTHR   256

// ---------------- device scratch (static: no allocations allowed) ----------------
// Transposed triplane: [12 planes][256 y][256 x][32 c]  (channel-contiguous, 128B/texel)
__device__ __align__(16) float g_tp[12 * RES * RES * TD];
// Transposed weights, k-major [k][128]:
//   [0 .. 8703]        w_in^T   (68x128)
//   [8704 .. 17407]    w_skip^T (68x128)
//   [17408 + l*16384]  hidden layer l (before0, before1, after0, after1), each 128x128
__device__ __align__(16) float g_w[2 * FIN * HID + 4 * HID * HID];

// ---------------- f32x2 helpers ----------------
__device__ __forceinline__ unsigned long long pack_dup(float x) {
    unsigned long long d;
    unsigned int xi = __float_as_uint(x);
    asm("mov.b64 %0, {%1, %2};" : "=l"(d) : "r"(xi), "r"(xi));
    return d;
}
__device__ __forceinline__ void fma2(unsigned long long& acc, unsigned long long a, unsigned long long b) {
    asm("fma.rn.f32x2 %0, %1, %2, %0;" : "+l"(acc) : "l"(a), "l"(b));
}
__device__ __forceinline__ void unpack2(unsigned long long v, float& lo, float& hi) {
    unsigned int a, b;
    asm("mov.b64 {%0, %1}, %2;" : "=r"(a), "=r"(b) : "l"(v));
    lo = __uint_as_float(a);
    hi = __uint_as_float(b);
}

// ---------------- prep kernel 1: triplane transpose [C][HW] -> [HW][C] ----------------
__global__ void tp_transpose_kernel(const float* __restrict__ tri) {
    __shared__ float t[32][33];
    int n   = blockIdx.y;           // plane 0..11
    int hw0 = blockIdx.x * 32;      // 65536/32 = 2048 chunks
    int tx  = threadIdx.x;          // 0..31
    int ty  = threadIdx.y;          // 0..7
    #pragma unroll
    for (int cc = ty; cc < 32; cc += 8)
        t[cc][tx] = tri[(n * TD + cc) * (RES * RES) + hw0 + tx];
    __syncthreads();
    #pragma unroll
    for (int r = ty; r < 32; r += 8)
        g_tp[((size_t)n * (RES * RES) + hw0 + r) * TD + tx] = t[tx][r];
}

// ---------------- prep kernel 2: weight transpose to k-major ----------------
__global__ void prep_weights_kernel(const float* __restrict__ w_in,
                                    const float* __restrict__ w_skip,
                                    const float* __restrict__ w_before,
                                    const float* __restrict__ w_after) {
    int idx = blockIdx.x * blockDim.x + threadIdx.x;
    const int NIN = FIN * HID;  // 8704
    if (idx < NIN) {
        int k = idx >> 7, o = idx & 127;
        g_w[idx] = w_in[o * FIN + k];
    } else if (idx < 2 * NIN) {
        int r = idx - NIN;
        int k = r >> 7, o = r & 127;
        g_w[idx] = w_skip[o * FIN + k];
    } else if (idx < 2 * NIN + 4 * HID * HID) {
        int r = idx - 2 * NIN;
        int l = r >> 14;
        int e = r & 16383;
        int k = e >> 7, o = e & 127;
        float v = (l < 2) ? w_before[l * HID * HID + o * HID + k]
                          : w_after[(l - 2) * HID * HID + o * HID + k];
        g_w[idx] = v;
    }
}

// ---------------- fused GEMM layer (f32x2) ----------------
// wS: [K][128] k-major in smem.  src: [K][NP].  dst: [128][NP].  bias: [128].
// Thread computes 8 outs (o0..o0+7) x 4 points (p0..p0+3).
template <int K, bool ADD>
__device__ __forceinline__ void mlp_layer(const float* __restrict__ wS,
                                          const float* __restrict__ bias,
                                          const float* __restrict__ src,
                                          float* __restrict__ dst,
                                          const float* __restrict__ addsrc,
                                          int og, int pg) {
    const int o0 = og * 8;
    const int p0 = pg * 4;
    unsigned long long acc[4][4];
    #pragma unroll
    for (int op = 0; op < 4; op++) {
        unsigned long long bp = *(const unsigned long long*)(bias + o0 + 2 * op);
        #pragma unroll
        for (int j = 0; j < 4; j++) acc[op][j] = bp;
    }
    const float* xptr = src + p0;
    const float* wptr = wS + o0;
    #pragma unroll 4
    for (int k = 0; k < K; k++) {
        float4 xv = *(const float4*)(xptr);
        ulonglong2 wa = *(const ulonglong2*)(wptr);      // pairs (o0,o0+1),(o0+2,o0+3)
        ulonglong2 wb = *(const ulonglong2*)(wptr + 4);  // pairs (o0+4,o0+5),(o0+6,o0+7)
        xptr += NP;
        wptr += HID;
        unsigned long long xs0 = pack_dup(xv.x);
        unsigned long long xs1 = pack_dup(xv.y);
        unsigned long long xs2 = pack_dup(xv.z);
        unsigned long long xs3 = pack_dup(xv.w);
        fma2(acc[0][0], wa.x, xs0); fma2(acc[1][0], wa.y, xs0);
        fma2(acc[2][0], wb.x, xs0); fma2(acc[3][0], wb.y, xs0);
        fma2(acc[0][1], wa.x, xs1); fma2(acc[1][1], wa.y, xs1);
        fma2(acc[2][1], wb.x, xs1); fma2(acc[3][1], wb.y, xs1);
        fma2(acc[0][2], wa.x, xs2); fma2(acc[1][2], wa.y, xs2);
        fma2(acc[2][2], wb.x, xs2); fma2(acc[3][2], wb.y, xs2);
        fma2(acc[0][3], wa.x, xs3); fma2(acc[1][3], wa.y, xs3);
        fma2(acc[2][3], wb.x, xs3); fma2(acc[3][3], wb.y, xs3);
    }
    #pragma unroll
    for (int op = 0; op < 4; op++) {
        int o = o0 + 2 * op;
        #pragma unroll
        for (int j = 0; j < 4; j++) {
            float lo, hi;
            unpack2(acc[op][j], lo, hi);
            lo = fmaxf(lo, 0.0f);
            hi = fmaxf(hi, 0.0f);
            int p = p0 + j;
            if (ADD) {
                lo += addsrc[o * NP + p];
                hi += addsrc[(o + 1) * NP + p];
            }
            dst[o * NP + p]       = lo;
            dst[(o + 1) * NP + p] = hi;
        }
    }
}

__device__ __forceinline__ void stage_w(float* __restrict__ wS,
                                        const float* __restrict__ src, int nf4, int tx) {
    float4* d = (float4*)wS;
    const float4* s = (const float4*)src;
    for (int i = tx; i < nf4; i += NTHR) d[i] = s[i];
}

// ---------------- main fused decoder kernel ----------------
// smem layout (floats):
//   hT [68][64]       @ 0
//   A  [128][64]      @ 4352
//   Bf [128][64]      @ 12544
//   wS [128][128]     @ 20736
//   bS [772]          @ 37120   (b_in | b_before0 | b_before1 | b_skip | b_after0 | b_after1 | b_out)
//   cS [64*3]         @ 37892
#define SM_HT 0
#define SM_A  4352
#define SM_B  12544
#define SM_W  20736
#define SM_BI 37120
#define SM_C  37892
#define SM_FLOATS 38084
#define SMEM_BYTES (SM_FLOATS * 4)

__global__ void __launch_bounds__(NTHR, 1)
decoder_kernel(const float* __restrict__ coords,
               const float* __restrict__ b_in,
               const float* __restrict__ b_skip,
               const float* __restrict__ b_before,
               const float* __restrict__ b_after,
               const float* __restrict__ w_out,
               const float* __restrict__ b_out,
               float* __restrict__ out) {
    extern __shared__ float smem[];
    float* hT = smem + SM_HT;
    float* A  = smem + SM_A;
    float* Bf = smem + SM_B;
    float* wS = smem + SM_W;
    float* bS = smem + SM_BI;
    float* cS = smem + SM_C;

    const int tx   = threadIdx.x;
    const int base = blockIdx.x * NP;

    // ---- load coords + biases ----
    for (int i = tx; i < NP * 3; i += NTHR) cS[i] = coords[base * 3 + i];
    for (int i = tx; i < 772; i += NTHR) {
        float v;
        if (i < 128)       v = b_in[i];
        else if (i < 384)  v = b_before[i - 128];
        else if (i < 512)  v = b_skip[i - 384];
        else if (i < 768)  v = b_after[i - 512];
        else               v = b_out[i - 768];
        bS[i] = v;
    }
    __syncthreads();

    // ---- encode + gather: 4 threads per point ----
    {
        const int p = tx >> 2;
        const int q = tx & 3;
        const float c0 = cS[p * 3 + 0];
        const float c1 = cS[p * 3 + 1];
        const float c2 = cS[p * 3 + 2];
        const float nrm[3] = {(c0 + 1.0f) * 0.5f, (c1 + 1.0f) * 0.5f, (c2 + 1.0f) * 0.5f};

        // frequency encoding: rows [d*12 + k] = sin, [d*12 + 6 + k] = cos
        for (int a = q; a < 18; a += 4) {
            int d = a / 6;
            int k = a - 6 * d;
            float freq = 3.14159265358979f * (float)(1 << k);
            float s, c;
            sincosf(nrm[d] * freq, &s, &c);
            hT[(d * 12 + k) * NP + p]     = s;
            hT[(d * 12 + 6 + k) * NP + p] = c;
        }

        // triplane bilinear gather: thread handles channels q*8 .. q*8+7
        const int b = (base + p) >> 16;  // P = 65536
        const float gpx[3] = {c0, c0, c1};
        const float gpy[3] = {c1, c2, c2};
        float acc[8];
        #pragma unroll
        for (int j = 0; j < 8; j++) acc[j] = 0.0f;

        #pragma unroll
        for (int pl = 0; pl < 3; pl++) {
            float ix = (gpx[pl] + 1.0f) * 127.5f;
            float iy = (gpy[pl] + 1.0f) * 127.5f;
            float x0f = floorf(ix), y0f = floorf(iy);
            float fx = ix - x0f, fy = iy - y0f;
            int x0 = (int)x0f, y0 = (int)y0f;
            x0 = min(max(x0, 0), RES - 2);
            y0 = min(max(y0, 0), RES - 2);
            float w00 = (1.0f - fx) * (1.0f - fy);
            float w10 = fx * (1.0f - fy);
            float w01 = (1.0f - fx) * fy;
            float w11 = fx * fy;
            const float* bp = g_tp + ((size_t)(b * 3 + pl) * (RES * RES) + y0 * RES + x0) * TD + q * 8;
            float4 v00a = *(const float4*)(bp);
            float4 v00b = *(const float4*)(bp + 4);
            float4 v10a = *(const float4*)(bp + TD);
            float4 v10b = *(const float4*)(bp + TD + 4);
            float4 v01a = *(const float4*)(bp + RES * TD);
            float4 v01b = *(const float4*)(bp + RES * TD + 4);
            float4 v11a = *(const float4*)(bp + RES * TD + TD);
            float4 v11b = *(const float4*)(bp + RES * TD + TD + 4);
            acc[0] += w00 * v00a.x + w10 * v10a.x + w01 * v01a.x + w11 * v11a.x;
            acc[1] += w00 * v00a.y + w10 * v10a.y + w01 * v01a.y + w11 * v11a.y;
            acc[2] += w00 * v00a.z + w10 * v10a.z + w01 * v01a.z + w11 * v11a.z;
            acc[3] += w00 * v00a.w + w10 * v10a.w + w01 * v01a.w + w11 * v11a.w;
            acc[4] += w00 * v00b.x + w10 * v10b.x + w01 * v01b.x + w11 * v11b.x;
            acc[5] += w00 * v00b.y + w10 * v10b.y + w01 * v01b.y + w11 * v11b.y;
            acc[6] += w00 * v00b.z + w10 * v10b.z + w01 * v01b.z + w11 * v11b.z;
            acc[7] += w00 * v00b.w + w10 * v10b.w + w01 * v01b.w + w11 * v11b.w;
        }
        #pragma unroll
        for (int j = 0; j < 8; j++) hT[(CD + q * 8 + j) * NP + p] = acc[j];
    }

    // ---- MLP ----
    const int og = tx >> 4;  // 0..15 (x8 outs)
    const int pg = tx & 15;  // 0..15 (x4 points)
    const int NIN4  = FIN * HID / 4;  // 2176
    const int NHID4 = HID * HID / 4;  // 4096

    stage_w(wS, g_w, NIN4, tx);
    __syncthreads();
    mlp_layer<FIN, false>(wS, bS + 0, hT, A, nullptr, og, pg);       // x1 = relu(Win h)
    __syncthreads();
    stage_w(wS, g_w + 2 * FIN * HID, NHID4, tx);
    __syncthreads();
    mlp_layer<HID, false>(wS, bS + 128, A, Bf, nullptr, og, pg);     // x2 = relu(W0 x1)
    __syncthreads();
    stage_w(wS, g_w + 2 * FIN * HID + HID * HID, NHID4, tx);
    __syncthreads();
    mlp_layer<HID, false>(wS, bS + 256, Bf, A, nullptr, og, pg);     // x3 = relu(W1 x2)
    __syncthreads();
    stage_w(wS, g_w + FIN * HID, NIN4, tx);
    __syncthreads();
    mlp_layer<FIN, true>(wS, bS + 384, hT, Bf, A, og, pg);           // x4 = x3 + relu(Wskip h)
    __syncthreads();
    stage_w(wS, g_w + 2 * FIN * HID + 2 * HID * HID, NHID4, tx);
    __syncthreads();
    mlp_layer<HID, false>(wS, bS + 512, Bf, A, nullptr, og, pg);     // x5 = relu(W2 x4)
    __syncthreads();
    stage_w(wS, g_w + 2 * FIN * HID + 3 * HID * HID, NHID4, tx);
    __syncthreads();
    mlp_layer<HID, false>(wS, bS + 640, A, Bf, nullptr, og, pg);     // x6 = relu(W3 x5)
    __syncthreads();

    // ---- output layer: 4 outs x 64 points = 256 threads ----
    stage_w(wS, w_out, (4 * HID) / 4, tx);  // [o][k] row-major, used directly
    __syncthreads();
    {
        const int o  = tx & 3;
        const int p  = tx >> 2;
        float acc = bS[768 + o];
        const float* wr = wS + o * HID;
        const float* xr = Bf + p;
        #pragma unroll 8
        for (int k = 0; k < HID; k++) acc += wr[k] * xr[k * NP];
        const int gp = base + p;
        if (o < 3) {
            out[gp * 3 + o] = 1.0f / (1.0f + expf(-acc));
        } else {
            float c0 = cS[p * 3 + 0], c1 = cS[p * 3 + 1], c2 = cS[p * 3 + 2];
            bool sel = (c0 > -1.0f) && (c0 < 1.0f) &&
                       (c1 > -1.0f) && (c1 < 1.0f) &&
                       (c2 > -1.0f) && (c2 < 1.0f);
            out[3 * NPTS + gp] = sel ? expf(acc - 1.0f) : 0.0f;
        }
    }
}

// ---------------- launch ----------------
extern "C" void kernel_launch(void* const* d_in, const int* in_sizes, int n_in,
                              void* d_out, int out_size) {
    const float* triplane = (const float*)d_in[0];
    const float* coords   = (const float*)d_in[1];
    const float* w_in     = (const float*)d_in[2];
    const float* b_in     = (const float*)d_in[3];
    const float* w_skip   = (const float*)d_in[4];
    const float* b_skip   = (const float*)d_in[5];
    const float* w_before = (const float*)d_in[6];
    const float* b_before = (const float*)d_in[7];
    const float* w_after  = (const float*)d_in[8];
    const float* b_after  = (const float*)d_in[9];
    const float* w_out    = (const float*)d_in[10];
    const float* b_out    = (const float*)d_in[11];
    float* out = (float*)d_out;

    static bool attr_set = false;
    if (!attr_set) {
        cudaFuncSetAttribute(decoder_kernel,
                             cudaFuncAttributeMaxDynamicSharedMemorySize, SMEM_BYTES);
        attr_set = true;
    }

    tp_transpose_kernel<<<dim3(RES * RES / 32, 12), dim3(32, 8)>>>(triplane);
    prep_weights_kernel<<<(2 * FIN * HID + 4 * HID * HID + 255) / 256, 256>>>(
        w_in, w_skip, w_before, w_after);
    decoder_kernel<<<NPTS / NP, NTHR, SMEM_BYTES>>>(
        coords, b_in, b_skip, b_before, b_after, w_out, b_out, out);
}

// round 3
// speedup vs baseline: 2.0221x; 2.0221x over previous
#include <cuda_runtime.h>
#include <cuda_bf16.h>
#include <math.h>
#include <stdint.h>

// ---------------- problem constants ----------------
#define BB     4
#define PP     65536
#define NPTS   (BB * PP)
#define TD     32
#define HID    128
#define CD     36
#define FIN    68
#define RES    256

#define NP     128              // points per CTA
#define NTHR   256              // 8 warps
#define STRIDE 136              // padded row stride (elems)
#define ROWB   (STRIDE * 2)     // 272 bytes per row
#define PLANE  (128 * ROWB)     // 34816 bytes per 128-row bf16 plane

// smem layout (bytes): [X_hi][X_lo][H_hi][H_lo][W_hi][W_lo][bias][coords]
#define X_HI      0
#define H_HI      (2 * PLANE)       // 69632
#define W_HI      (4 * PLANE)       // 139264
#define SM_BIAS   (6 * PLANE)       // 208896
#define SM_COORD  (SM_BIAS + 772 * 4)
#define SMEM_BYTES (SM_COORD + NP * 3 * 4)   // 213520

// ---------------- device scratch ----------------
__device__ __align__(16) float g_tp[12 * RES * RES * TD];
// packed weights: 6 hidden slots x (hi PLANE + lo PLANE), then w_out (8 rows): hi 2176 + lo 2176
__device__ __align__(16) unsigned char g_wp[6 * 2 * PLANE + 2 * 8 * ROWB];

// ---------------- helpers ----------------
__device__ __forceinline__ uint32_t smem_u32(const void* p) {
    uint32_t a;
    asm("{ .reg .u64 t; cvta.to.shared.u64 t, %1; cvt.u32.u64 %0, t; }" : "=r"(a) : "l"(p));
    return a;
}
__device__ __forceinline__ uint32_t packbf(float lo, float hi) {
    uint32_t r;
    asm("cvt.rn.bf16x2.f32 %0, %1, %2;" : "=r"(r) : "f"(hi), "f"(lo));
    return r;
}
__device__ __forceinline__ float bfLow(uint32_t h)  { return __uint_as_float(h << 16); }
__device__ __forceinline__ float bfHigh(uint32_t h) { return __uint_as_float(h & 0xFFFF0000u); }

__device__ __forceinline__ void ldsm4(uint32_t a, uint32_t r[4]) {
    asm volatile("ldmatrix.sync.aligned.m8n8.x4.shared.b16 {%0,%1,%2,%3}, [%4];"
                 : "=r"(r[0]), "=r"(r[1]), "=r"(r[2]), "=r"(r[3]) : "r"(a));
}
__device__ __forceinline__ void ldsm2(uint32_t a, uint32_t r[2]) {
    asm volatile("ldmatrix.sync.aligned.m8n8.x2.shared.b16 {%0,%1}, [%2];"
                 : "=r"(r[0]), "=r"(r[1]) : "r"(a));
}
__device__ __forceinline__ void mma16816(float d[4], const uint32_t a[4], const uint32_t b[2]) {
    asm volatile("mma.sync.aligned.m16n8k16.row.col.f32.bf16.bf16.f32 "
                 "{%0,%1,%2,%3}, {%4,%5,%6,%7}, {%8,%9}, {%0,%1,%2,%3};"
                 : "+f"(d[0]), "+f"(d[1]), "+f"(d[2]), "+f"(d[3])
                 : "r"(a[0]), "r"(a[1]), "r"(a[2]), "r"(a[3]), "r"(b[0]), "r"(b[1]));
}

// ---------------- prep kernel 1: triplane transpose [C][HW] -> [HW][C] ----------------
__global__ void tp_transpose_kernel(const float* __restrict__ tri) {
    __shared__ float t[32][33];
    int n   = blockIdx.y;
    int hw0 = blockIdx.x * 32;
    int tx  = threadIdx.x;
    int ty  = threadIdx.y;
    #pragma unroll
    for (int cc = ty; cc < 32; cc += 8)
        t[cc][tx] = tri[(n * TD + cc) * (RES * RES) + hw0 + tx];
    __syncthreads();
    #pragma unroll
    for (int r = ty; r < 32; r += 8)
        g_tp[((size_t)n * (RES * RES) + hw0 + r) * TD + tx] = t[tx][r];
}

// ---------------- prep kernel 2: split weights to bf16 hi/lo, padded stride ----------------
// slots: 0=w_in, 1=w_before0, 2=w_skip, 3=w_before1, 4=w_after0, 5=w_after1, 6=w_out(8 rows)
__global__ void prep_w_kernel(const float* __restrict__ w_in,
                              const float* __restrict__ w_skip,
                              const float* __restrict__ w_before,
                              const float* __restrict__ w_after,
                              const float* __restrict__ w_out) {
    const int HN  = 6 * 128 * STRIDE;        // 104448
    const int TOT = HN + 8 * STRIDE;         // + 1088
    int idx = blockIdx.x * blockDim.x + threadIdx.x;
    if (idx >= TOT) return;
    int slot, o, k, planeB;
    size_t sbase;
    if (idx < HN) {
        slot = idx / (128 * STRIDE);
        int e = idx % (128 * STRIDE);
        o = e / STRIDE; k = e % STRIDE;
        sbase = (size_t)slot * 2 * PLANE;
        planeB = PLANE;
    } else {
        slot = 6;
        int e = idx - HN;
        o = e / STRIDE; k = e % STRIDE;
        sbase = (size_t)6 * 2 * PLANE;
        planeB = 8 * ROWB;
    }
    float v = 0.0f;
    switch (slot) {
        case 0: if (k < FIN) v = w_in[o * FIN + k]; break;
        case 1: if (k < HID) v = w_before[o * HID + k]; break;
        case 2: if (k < FIN) v = w_skip[o * FIN + k]; break;
        case 3: if (k < HID) v = w_before[HID * HID + o * HID + k]; break;
        case 4: if (k < HID) v = w_after[o * HID + k]; break;
        case 5: if (k < HID) v = w_after[HID * HID + o * HID + k]; break;
        case 6: if (o < 4 && k < HID) v = w_out[o * HID + k]; break;
    }
    __nv_bfloat16 hi = __float2bfloat16(v);
    __nv_bfloat16 lo = __float2bfloat16(v - __bfloat162float(hi));
    size_t off = (size_t)(o * STRIDE + k) * 2;
    *(__nv_bfloat16*)(g_wp + sbase + off)          = hi;
    *(__nv_bfloat16*)(g_wp + sbase + planeB + off) = lo;
}

// ---------------- decoder pieces ----------------
__device__ __forceinline__ void stage(unsigned char* sm, const unsigned char* src,
                                      int planeBytes, int tid) {
    uint4* dh = (uint4*)(sm + W_HI);
    uint4* dl = (uint4*)(sm + W_HI + PLANE);
    const uint4* shp = (const uint4*)src;
    const uint4* slp = (const uint4*)(src + planeBytes);
    int n = planeBytes >> 4;
    for (int i = tid; i < n; i += NTHR) { dh[i] = shp[i]; dl[i] = slp[i]; }
}

// one MLP layer: D[pt16 x 128] += Ahi*Bhi + Ahi*Blo + Alo*Bhi.  lo planes at +PLANE.
template <int KS, int NT>
__device__ __forceinline__ void mma_layer(uint32_t aHi, uint32_t bHi, float D[][4]) {
    #pragma unroll
    for (int nt = 0; nt < NT; nt++) {
        D[nt][0] = 0.f; D[nt][1] = 0.f; D[nt][2] = 0.f; D[nt][3] = 0.f;
    }
    #pragma unroll 2
    for (int k = 0; k < KS; k++) {
        uint32_t Ah[4], Al[4];
        ldsm4(aHi + k * 32, Ah);
        ldsm4(aHi + PLANE + k * 32, Al);
        #pragma unroll
        for (int nt = 0; nt < NT; nt++) {
            uint32_t Bh[2], Bl[2];
            ldsm2(bHi + nt * (8 * ROWB) + k * 32, Bh);
            ldsm2(bHi + PLANE + nt * (8 * ROWB) + k * 32, Bl);
            mma16816(D[nt], Ah, Bh);
            mma16816(D[nt], Ah, Bl);
            mma16816(D[nt], Al, Bh);
        }
    }
}

// epilogue: bias + relu (+ skip combine), split to bf16 hi/lo, store into X operand
template <bool SK>
__device__ __forceinline__ void epi(unsigned char* sm, float D[][4], float S[][4],
                                    const float* bd, const float* bs, int pA, int tig) {
    const int rowA = pA * ROWB;
    const int rowB = rowA + 8 * ROWB;
    #pragma unroll
    for (int nt = 0; nt < 16; nt++) {
        int c0 = nt * 8 + 2 * tig;
        float b0 = bd[c0], b1 = bd[c0 + 1];
        float x0 = fmaxf(D[nt][0] + b0, 0.f), x1 = fmaxf(D[nt][1] + b1, 0.f);
        float x2 = fmaxf(D[nt][2] + b0, 0.f), x3 = fmaxf(D[nt][3] + b1, 0.f);
        if (SK) {
            float s0 = bs[c0], s1 = bs[c0 + 1];
            x0 += fmaxf(S[nt][0] + s0, 0.f); x1 += fmaxf(S[nt][1] + s1, 0.f);
            x2 += fmaxf(S[nt][2] + s0, 0.f); x3 += fmaxf(S[nt][3] + s1, 0.f);
        }
        uint32_t h0 = packbf(x0, x1), h1 = packbf(x2, x3);
        uint32_t l0 = packbf(x0 - bfLow(h0), x1 - bfHigh(h0));
        uint32_t l1 = packbf(x2 - bfLow(h1), x3 - bfHigh(h1));
        int off = c0 * 2;
        *(uint32_t*)(sm + X_HI + rowA + off)         = h0;
        *(uint32_t*)(sm + X_HI + PLANE + rowA + off) = l0;
        *(uint32_t*)(sm + X_HI + rowB + off)         = h1;
        *(uint32_t*)(sm + X_HI + PLANE + rowB + off) = l1;
    }
}

// ---------------- main decoder kernel ----------------
__global__ void __launch_bounds__(NTHR, 1)
decoder_kernel(const float* __restrict__ coords,
               const float* __restrict__ b_in,
               const float* __restrict__ b_skip,
               const float* __restrict__ b_before,
               const float* __restrict__ b_after,
               const float* __restrict__ b_out,
               float* __restrict__ out) {
    extern __shared__ unsigned char sm[];
    const uint32_t sb = smem_u32(sm);
    const int tid  = threadIdx.x;
    const int lane = tid & 31;
    const int warp = tid >> 5;
    const int base = blockIdx.x * NP;

    float* bS = (float*)(sm + SM_BIAS);
    float* cS = (float*)(sm + SM_COORD);

    // coords + biases
    for (int i = tid; i < NP * 3; i += NTHR) cS[i] = coords[base * 3 + i];
    for (int i = tid; i < 772; i += NTHR) {
        float v;
        if (i < 128)      v = b_in[i];
        else if (i < 256) v = b_skip[i - 128];
        else if (i < 512) v = b_before[i - 256];
        else if (i < 768) v = b_after[i - 512];
        else              v = b_out[i - 768];
        bS[i] = v;
    }
    // zero H pad cols 68..79 (hi+lo)
    {
        int p = tid >> 1, q = tid & 1;
        #pragma unroll
        for (int j = 0; j < 6; j++) {
            int k = FIN + q * 6 + j;
            int off = (p * STRIDE + k) * 2;
            *(uint16_t*)(sm + H_HI + off)         = 0;
            *(uint16_t*)(sm + H_HI + PLANE + off) = 0;
        }
    }
    __syncthreads();

    // ---- gather + freq encode -> H (bf16 hi/lo) ----
    {
        const int p = tid >> 1;
        const int q = tid & 1;
        const float c0 = cS[p * 3 + 0];
        const float c1 = cS[p * 3 + 1];
        const float c2 = cS[p * 3 + 2];
        const float nrm[3] = {(c0 + 1.0f) * 0.5f, (c1 + 1.0f) * 0.5f, (c2 + 1.0f) * 0.5f};

        for (int a = q; a < 18; a += 2) {
            int d = a / 6;
            int k = a - 6 * d;
            float freq = 3.14159265358979f * (float)(1 << k);
            float s, c;
            sincosf(nrm[d] * freq, &s, &c);
            int k1 = d * 12 + k, k2 = d * 12 + 6 + k;
            int o1 = (p * STRIDE + k1) * 2, o2 = (p * STRIDE + k2) * 2;
            __nv_bfloat16 h1 = __float2bfloat16(s);
            __nv_bfloat16 h2 = __float2bfloat16(c);
            *(__nv_bfloat16*)(sm + H_HI + o1)         = h1;
            *(__nv_bfloat16*)(sm + H_HI + PLANE + o1) = __float2bfloat16(s - __bfloat162float(h1));
            *(__nv_bfloat16*)(sm + H_HI + o2)         = h2;
            *(__nv_bfloat16*)(sm + H_HI + PLANE + o2) = __float2bfloat16(c - __bfloat162float(h2));
        }

        const int b = (base + p) >> 16;
        const float gpx[3] = {c0, c0, c1};
        const float gpy[3] = {c1, c2, c2};
        float acc[16];
        #pragma unroll
        for (int j = 0; j < 16; j++) acc[j] = 0.0f;

        #pragma unroll
        for (int pl = 0; pl < 3; pl++) {
            float ix = (gpx[pl] + 1.0f) * 127.5f;
            float iy = (gpy[pl] + 1.0f) * 127.5f;
            float x0f = floorf(ix), y0f = floorf(iy);
            float fx = ix - x0f, fy = iy - y0f;
            int x0 = min(max((int)x0f, 0), RES - 2);
            int y0 = min(max((int)y0f, 0), RES - 2);
            float w00 = (1.0f - fx) * (1.0f - fy);
            float w10 = fx * (1.0f - fy);
            float w01 = (1.0f - fx) * fy;
            float w11 = fx * fy;
            const float* bp = g_tp + ((size_t)(b * 3 + pl) * (RES * RES) + y0 * RES + x0) * TD + q * 16;
            #pragma unroll
            for (int c = 0; c < 4; c++) {
                float4 v00 = *(const float4*)(bp + c * 4);
                float4 v10 = *(const float4*)(bp + TD + c * 4);
                float4 v01 = *(const float4*)(bp + RES * TD + c * 4);
                float4 v11 = *(const float4*)(bp + RES * TD + TD + c * 4);
                acc[c * 4 + 0] += w00 * v00.x + w10 * v10.x + w01 * v01.x + w11 * v11.x;
                acc[c * 4 + 1] += w00 * v00.y + w10 * v10.y + w01 * v01.y + w11 * v11.y;
                acc[c * 4 + 2] += w00 * v00.z + w10 * v10.z + w01 * v01.z + w11 * v11.z;
                acc[c * 4 + 3] += w00 * v00.w + w10 * v10.w + w01 * v01.w + w11 * v11.w;
            }
        }
        #pragma unroll
        for (int j = 0; j < 16; j++) {
            int k = CD + q * 16 + j;
            int off = (p * STRIDE + k) * 2;
            __nv_bfloat16 h = __float2bfloat16(acc[j]);
            *(__nv_bfloat16*)(sm + H_HI + off)         = h;
            *(__nv_bfloat16*)(sm + H_HI + PLANE + off) = __float2bfloat16(acc[j] - __bfloat162float(h));
        }
    }

    // per-thread fragment addresses
    const uint32_t aSel = (uint32_t)(((warp * 16 + (lane & 15)) * STRIDE + ((lane >> 4) * 8)) * 2);
    const uint32_t aX = sb + X_HI + aSel;
    const uint32_t aH = sb + H_HI + aSel;
    const uint32_t bW = sb + W_HI +
        (uint32_t)((((lane & 7)) * STRIDE + (((lane >> 3) & 1) * 8)) * 2);

    const int g   = lane >> 2;
    const int tig = lane & 3;
    const int pA  = warp * 16 + g;

    float D[16][4];
    float S[16][4];

    // L1: x1 = relu(Win h)
    stage(sm, g_wp + 0 * 2 * PLANE, PLANE, tid);
    __syncthreads();
    mma_layer<5, 16>(aH, bW, D);
    __syncthreads();
    epi<false>(sm, D, S, bS + 0, nullptr, pA, tig);
    stage(sm, g_wp + 1 * 2 * PLANE, PLANE, tid);
    __syncthreads();

    // L2: x2 = relu(W0 x1)
    mma_layer<8, 16>(aX, bW, D);
    __syncthreads();
    epi<false>(sm, D, S, bS + 256, nullptr, pA, tig);
    stage(sm, g_wp + 2 * 2 * PLANE, PLANE, tid);
    __syncthreads();

    // skip: S = Wskip h (kept in regs)
    mma_layer<5, 16>(aH, bW, S);
    __syncthreads();
    stage(sm, g_wp + 3 * 2 * PLANE, PLANE, tid);
    __syncthreads();

    // L3: x4 = relu(W1 x2 + b) + relu(S + bskip)
    mma_layer<8, 16>(aX, bW, D);
    __syncthreads();
    epi<true>(sm, D, S, bS + 384, bS + 128, pA, tig);
    stage(sm, g_wp + 4 * 2 * PLANE, PLANE, tid);
    __syncthreads();

    // L4: x5 = relu(W2 x4)
    mma_layer<8, 16>(aX, bW, D);
    __syncthreads();
    epi<false>(sm, D, S, bS + 512, nullptr, pA, tig);
    stage(sm, g_wp + 5 * 2 * PLANE, PLANE, tid);
    __syncthreads();

    // L5: x6 = relu(W3 x5)
    mma_layer<8, 16>(aX, bW, D);
    __syncthreads();
    epi<false>(sm, D, S, bS + 640, nullptr, pA, tig);
    stage(sm, g_wp + 6 * 2 * PLANE, 8 * ROWB, tid);
    __syncthreads();

    // L6: out = Wout x6  (single n-tile; cols 0..3 valid)
    mma_layer<8, 1>(aX, bW, D);

    // final epilogue
    {
        const int pB  = pA + 8;
        const int gpA = base + pA, gpB = base + pB;
        if (tig == 0) {
            float v0 = D[0][0] + bS[768], v1 = D[0][1] + bS[769];
            float v2 = D[0][2] + bS[768], v3 = D[0][3] + bS[769];
            out[gpA * 3 + 0] = 1.0f / (1.0f + expf(-v0));
            out[gpA * 3 + 1] = 1.0f / (1.0f + expf(-v1));
            out[gpB * 3 + 0] = 1.0f / (1.0f + expf(-v2));
            out[gpB * 3 + 1] = 1.0f / (1.0f + expf(-v3));
        } else if (tig == 1) {
            float v0 = D[0][0] + bS[770], v1 = D[0][1] + bS[771];
            float v2 = D[0][2] + bS[770], v3 = D[0][3] + bS[771];
            out[gpA * 3 + 2] = 1.0f / (1.0f + expf(-v0));
            out[gpB * 3 + 2] = 1.0f / (1.0f + expf(-v2));
            float a0 = cS[pA * 3 + 0], a1 = cS[pA * 3 + 1], a2 = cS[pA * 3 + 2];
            bool selA = (a0 > -1.0f) && (a0 < 1.0f) && (a1 > -1.0f) && (a1 < 1.0f) &&
                        (a2 > -1.0f) && (a2 < 1.0f);
            float b0 = cS[pB * 3 + 0], b1 = cS[pB * 3 + 1], b2 = cS[pB * 3 + 2];
            bool selB = (b0 > -1.0f) && (b0 < 1.0f) && (b1 > -1.0f) && (b1 < 1.0f) &&
                        (b2 > -1.0f) && (b2 < 1.0f);
            out[3 * NPTS + gpA] = selA ? expf(v1 - 1.0f) : 0.0f;
            out[3 * NPTS + gpB] = selB ? expf(v3 - 1.0f) : 0.0f;
        }
    }
}

// ---------------- launch ----------------
extern "C" void kernel_launch(void* const* d_in, const int* in_sizes, int n_in,
                              void* d_out, int out_size) {
    const float* triplane = (const float*)d_in[0];
    const float* coords   = (const float*)d_in[1];
    const float* w_in     = (const float*)d_in[2];
    const float* b_in     = (const float*)d_in[3];
    const float* w_skip   = (const float*)d_in[4];
    const float* b_skip   = (const float*)d_in[5];
    const float* w_before = (const float*)d_in[6];
    const float* b_before = (const float*)d_in[7];
    const float* w_after  = (const float*)d_in[8];
    const float* b_after  = (const float*)d_in[9];
    const float* w_out    = (const float*)d_in[10];
    const float* b_out    = (const float*)d_in[11];
    float* out = (float*)d_out;

    static bool attr_set = false;
    if (!attr_set) {
        cudaFuncSetAttribute(decoder_kernel,
                             cudaFuncAttributeMaxDynamicSharedMemorySize, SMEM_BYTES);
        attr_set = true;
    }

    tp_transpose_kernel<<<dim3(RES * RES / 32, 12), dim3(32, 8)>>>(triplane);
    prep_w_kernel<<<(6 * 128 * STRIDE + 8 * STRIDE + 255) / 256, 256>>>(
        w_in, w_skip, w_before, w_after, w_out);
    decoder_kernel<<<NPTS / NP, NTHR, SMEM_BYTES>>>(
        coords, b_in, b_skip, b_before, b_after, b_out, out);
}

// round 4
// speedup vs baseline: 2.6019x; 1.2867x over previous
#include <cuda_runtime.h>
#include <cuda_bf16.h>
#include <math.h>
#include <stdint.h>

// ---------------- problem constants ----------------
#define BB     4
#define PP     65536
#define NPTS   (BB * PP)
#define TD     32
#define HID    128
#define CD     36
#define FIN    68
#define RES    256

#define NP     128              // points per CTA
#define NTHR   256              // 8 warps
#define STRIDE 136              // padded row stride (elems) for X and W
#define ROWB   (STRIDE * 2)     // 272 bytes per row
#define PLANE  (128 * ROWB)     // 34816 bytes per 128-row bf16 plane
#define HSTR   88               // H row stride (elems), K range 0..79
#define HROWB  (HSTR * 2)       // 176
#define HPLANE (128 * HROWB)    // 22528

// smem layout (bytes). H aliases the X region (H dies before first X write).
#define X_HI      0             // X hi plane; lo at +PLANE  (total 69632)
#define H_HI      0             // H hi plane; lo at +HPLANE (total 45056, aliased)
#define W_A       69632         // weight buffer A: hi, lo at +PLANE (total 69632)
#define W_B       139264        // weight buffer B
#define SM_BIAS   208896        // 772 floats
#define SM_COORD  211984        // 384 floats
#define SMEM_BYTES 213520

// ---------------- device scratch ----------------
__device__ __align__(16) float g_tp[12 * RES * RES * TD];
// slots 0=w_in 1=w_skip 2=w_b0 3=w_b1 4=w_a0 5=w_a1 (each hi PLANE + lo PLANE), 6=w_out (hi 2176 + lo 2176)
#define WSLOT (2 * PLANE)
__device__ __align__(16) unsigned char g_wp[6 * WSLOT + 2 * 8 * ROWB];

// ---------------- helpers ----------------
__device__ __forceinline__ uint32_t smem_u32(const void* p) {
    uint32_t a;
    asm("{ .reg .u64 t; cvta.to.shared.u64 t, %1; cvt.u32.u64 %0, t; }" : "=r"(a) : "l"(p));
    return a;
}
__device__ __forceinline__ uint32_t packbf(float lo, float hi) {
    uint32_t r;
    asm("cvt.rn.bf16x2.f32 %0, %1, %2;" : "=r"(r) : "f"(hi), "f"(lo));
    return r;
}
__device__ __forceinline__ float bfLow(uint32_t h)  { return __uint_as_float(h << 16); }
__device__ __forceinline__ float bfHigh(uint32_t h) { return __uint_as_float(h & 0xFFFF0000u); }

__device__ __forceinline__ void ldsm4(uint32_t a, uint32_t r[4]) {
    asm volatile("ldmatrix.sync.aligned.m8n8.x4.shared.b16 {%0,%1,%2,%3}, [%4];"
                 : "=r"(r[0]), "=r"(r[1]), "=r"(r[2]), "=r"(r[3]) : "r"(a));
}
__device__ __forceinline__ void ldsm2(uint32_t a, uint32_t r[2]) {
    asm volatile("ldmatrix.sync.aligned.m8n8.x2.shared.b16 {%0,%1}, [%2];"
                 : "=r"(r[0]), "=r"(r[1]) : "r"(a));
}
__device__ __forceinline__ void mma16816(float d[4], const uint32_t a[4], const uint32_t b[2]) {
    asm volatile("mma.sync.aligned.m16n8k16.row.col.f32.bf16.bf16.f32 "
                 "{%0,%1,%2,%3}, {%4,%5,%6,%7}, {%8,%9}, {%0,%1,%2,%3};"
                 : "+f"(d[0]), "+f"(d[1]), "+f"(d[2]), "+f"(d[3])
                 : "r"(a[0]), "r"(a[1]), "r"(a[2]), "r"(a[3]), "r"(b[0]), "r"(b[1]));
}

// cp.async
__device__ __forceinline__ void cpa_stage(uint32_t dst, const unsigned char* src, int bytes, int tid) {
    for (int i = tid * 16; i < bytes; i += NTHR * 16)
        asm volatile("cp.async.cg.shared.global [%0], [%1], 16;" :: "r"(dst + i), "l"(src + i) : "memory");
}
#define CPA_COMMIT()  asm volatile("cp.async.commit_group;" ::: "memory")
#define CPA_WAIT(N)   asm volatile("cp.async.wait_group %0;" :: "n"(N) : "memory")

// ---------------- prep kernel 1: triplane transpose [C][HW] -> [HW][C] ----------------
__global__ void tp_transpose_kernel(const float* __restrict__ tri) {
    __shared__ float t[32 * 129 + 4];
    const int n   = blockIdx.y;
    const int hw0 = blockIdx.x * 128;
    const int tid = threadIdx.x;
    const int c   = tid >> 3;   // 0..31
    const int h8  = tid & 7;    // 0..7
    const float* src = tri + (size_t)(n * 32 + c) * 65536 + hw0;
    #pragma unroll
    for (int i = 0; i < 4; i++) {
        int hw = i * 32 + h8 * 4;
        float4 v = *(const float4*)(src + hw);
        float* tr = t + c * 129 + hw;
        tr[0] = v.x; tr[1] = v.y; tr[2] = v.z; tr[3] = v.w;
    }
    __syncthreads();
    #pragma unroll
    for (int i = 0; i < 4; i++) {
        int e  = tid + 256 * i;
        int hw = e >> 3, c4 = e & 7;
        float4 v = make_float4(t[(4 * c4 + 0) * 129 + hw], t[(4 * c4 + 1) * 129 + hw],
                               t[(4 * c4 + 2) * 129 + hw], t[(4 * c4 + 3) * 129 + hw]);
        *(float4*)(g_tp + ((size_t)n * 65536 + hw0 + hw) * 32 + c4 * 4) = v;
    }
}

// ---------------- prep kernel 2: split weights to bf16 hi/lo ----------------
__global__ void prep_w_kernel(const float* __restrict__ w_in,
                              const float* __restrict__ w_skip,
                              const float* __restrict__ w_before,
                              const float* __restrict__ w_after,
                              const float* __restrict__ w_out) {
    const int HN  = 6 * 128 * STRIDE;
    const int TOT = HN + 8 * STRIDE;
    int idx = blockIdx.x * blockDim.x + threadIdx.x;
    if (idx >= TOT) return;
    int slot, o, k, planeB;
    size_t sbase;
    if (idx < HN) {
        slot = idx / (128 * STRIDE);
        int e = idx % (128 * STRIDE);
        o = e / STRIDE; k = e % STRIDE;
        sbase = (size_t)slot * WSLOT;
        planeB = PLANE;
    } else {
        slot = 6;
        int e = idx - HN;
        o = e / STRIDE; k = e % STRIDE;
        sbase = (size_t)6 * WSLOT;
        planeB = 8 * ROWB;
    }
    float v = 0.0f;
    switch (slot) {
        case 0: if (k < FIN) v = w_in[o * FIN + k]; break;
        case 1: if (k < FIN) v = w_skip[o * FIN + k]; break;
        case 2: if (k < HID) v = w_before[o * HID + k]; break;
        case 3: if (k < HID) v = w_before[HID * HID + o * HID + k]; break;
        case 4: if (k < HID) v = w_after[o * HID + k]; break;
        case 5: if (k < HID) v = w_after[HID * HID + o * HID + k]; break;
        case 6: if (o < 4 && k < HID) v = w_out[o * HID + k]; break;
    }
    __nv_bfloat16 hi = __float2bfloat16(v);
    __nv_bfloat16 lo = __float2bfloat16(v - __bfloat162float(hi));
    size_t off = (size_t)(o * STRIDE + k) * 2;
    *(__nv_bfloat16*)(g_wp + sbase + off)          = hi;
    *(__nv_bfloat16*)(g_wp + sbase + planeB + off) = lo;
}

// ---------------- MMA layers ----------------
// 16 n-tiles, B loaded with ldsm4 covering n-tile pairs. ALO = A lo-plane byte offset.
template <int KS, int ALO>
__device__ __forceinline__ void mma_layer16(uint32_t aHi, uint32_t bHi4, float D[16][4]) {
    #pragma unroll
    for (int nt = 0; nt < 16; nt++) { D[nt][0] = 0.f; D[nt][1] = 0.f; D[nt][2] = 0.f; D[nt][3] = 0.f; }
    #pragma unroll
    for (int k = 0; k < KS; k++) {
        uint32_t Ah[4], Al[4];
        ldsm4(aHi + k * 32, Ah);
        ldsm4(aHi + ALO + k * 32, Al);
        #pragma unroll
        for (int nt = 0; nt < 16; nt += 2) {
            uint32_t Bh[4], Bl[4];
            ldsm4(bHi4 + nt * (8 * ROWB) + k * 32, Bh);
            ldsm4(bHi4 + PLANE + nt * (8 * ROWB) + k * 32, Bl);
            mma16816(D[nt],     Ah, Bh);
            mma16816(D[nt],     Ah, Bl);
            mma16816(D[nt],     Al, Bh);
            mma16816(D[nt + 1], Ah, Bh + 2);
            mma16816(D[nt + 1], Ah, Bl + 2);
            mma16816(D[nt + 1], Al, Bh + 2);
        }
    }
}

// single n-tile (output layer)
template <int KS>
__device__ __forceinline__ void mma_layer1(uint32_t aHi, uint32_t bHi2, float d[4]) {
    d[0] = d[1] = d[2] = d[3] = 0.f;
    #pragma unroll
    for (int k = 0; k < KS; k++) {
        uint32_t Ah[4], Al[4], Bh[2], Bl[2];
        ldsm4(aHi + k * 32, Ah);
        ldsm4(aHi + PLANE + k * 32, Al);
        ldsm2(bHi2 + k * 32, Bh);
        ldsm2(bHi2 + PLANE + k * 32, Bl);
        mma16816(d, Ah, Bh);
        mma16816(d, Ah, Bl);
        mma16816(d, Al, Bh);
    }
}

// epilogue: bias + relu (+ skip combine), bf16 hi/lo split, store into X
template <bool SK>
__device__ __forceinline__ void epi(unsigned char* sm, float D[16][4], float S[16][4],
                                    const float* bd, const float* bs, int pA, int tig) {
    const int rowA = pA * ROWB;
    const int rowB = rowA + 8 * ROWB;
    #pragma unroll
    for (int nt = 0; nt < 16; nt++) {
        int c0 = nt * 8 + 2 * tig;
        float b0 = bd[c0], b1 = bd[c0 + 1];
        float x0 = fmaxf(D[nt][0] + b0, 0.f), x1 = fmaxf(D[nt][1] + b1, 0.f);
        float x2 = fmaxf(D[nt][2] + b0, 0.f), x3 = fmaxf(D[nt][3] + b1, 0.f);
        if (SK) {
            float s0 = bs[c0], s1 = bs[c0 + 1];
            x0 += fmaxf(S[nt][0] + s0, 0.f); x1 += fmaxf(S[nt][1] + s1, 0.f);
            x2 += fmaxf(S[nt][2] + s0, 0.f); x3 += fmaxf(S[nt][3] + s1, 0.f);
        }
        uint32_t h0 = packbf(x0, x1), h1 = packbf(x2, x3);
        uint32_t l0 = packbf(x0 - bfLow(h0), x1 - bfHigh(h0));
        uint32_t l1 = packbf(x2 - bfLow(h1), x3 - bfHigh(h1));
        int off = c0 * 2;
        *(uint32_t*)(sm + X_HI + rowA + off)         = h0;
        *(uint32_t*)(sm + X_HI + PLANE + rowA + off) = l0;
        *(uint32_t*)(sm + X_HI + rowB + off)         = h1;
        *(uint32_t*)(sm + X_HI + PLANE + rowB + off) = l1;
    }
}

// ---------------- main decoder kernel ----------------
__global__ void __launch_bounds__(NTHR, 1)
decoder_kernel(const float* __restrict__ coords,
               const float* __restrict__ b_in,
               const float* __restrict__ b_skip,
               const float* __restrict__ b_before,
               const float* __restrict__ b_after,
               const float* __restrict__ b_out,
               float* __restrict__ out) {
    extern __shared__ unsigned char sm[];
    const uint32_t sb = smem_u32(sm);
    const int tid  = threadIdx.x;
    const int lane = tid & 31;
    const int warp = tid >> 5;
    const int base = blockIdx.x * NP;

    float* bS = (float*)(sm + SM_BIAS);
    float* cS = (float*)(sm + SM_COORD);

    // kick off the first two weight stages immediately (overlap with gather)
    cpa_stage(sb + W_A, g_wp + 0 * WSLOT, WSLOT, tid); CPA_COMMIT();   // g0: w_in
    cpa_stage(sb + W_B, g_wp + 1 * WSLOT, WSLOT, tid); CPA_COMMIT();   // g1: w_skip

    // coords + biases
    for (int i = tid; i < NP * 3; i += NTHR) cS[i] = coords[base * 3 + i];
    for (int i = tid; i < 772; i += NTHR) {
        float v;
        if (i < 128)      v = b_in[i];
        else if (i < 256) v = b_skip[i - 128];
        else if (i < 512) v = b_before[i - 256];
        else if (i < 768) v = b_after[i - 512];
        else              v = b_out[i - 768];
        bS[i] = v;
    }
    // zero H pad cols 68..79 (hi+lo)
    {
        int p = tid >> 1, q = tid & 1;
        #pragma unroll
        for (int j = 0; j < 6; j++) {
            int k = FIN + q * 6 + j;
            int off = (p * HSTR + k) * 2;
            *(uint16_t*)(sm + H_HI + off)          = 0;
            *(uint16_t*)(sm + H_HI + HPLANE + off) = 0;
        }
    }
    __syncthreads();

    // ---- gather + freq encode -> H (bf16 hi/lo, stride 88) ----
    {
        const int p = tid >> 1;
        const int q = tid & 1;
        const float c0 = cS[p * 3 + 0];
        const float c1 = cS[p * 3 + 1];
        const float c2 = cS[p * 3 + 2];
        const float nrm[3] = {(c0 + 1.0f) * 0.5f, (c1 + 1.0f) * 0.5f, (c2 + 1.0f) * 0.5f};

        for (int a = q; a < 18; a += 2) {
            int d = a / 6;
            int k = a - 6 * d;
            float freq = 3.14159265358979f * (float)(1 << k);
            float s, c;
            sincosf(nrm[d] * freq, &s, &c);
            int k1 = d * 12 + k, k2 = d * 12 + 6 + k;
            int o1 = (p * HSTR + k1) * 2, o2 = (p * HSTR + k2) * 2;
            __nv_bfloat16 h1 = __float2bfloat16(s);
            __nv_bfloat16 h2 = __float2bfloat16(c);
            *(__nv_bfloat16*)(sm + H_HI + o1)          = h1;
            *(__nv_bfloat16*)(sm + H_HI + HPLANE + o1) = __float2bfloat16(s - __bfloat162float(h1));
            *(__nv_bfloat16*)(sm + H_HI + o2)          = h2;
            *(__nv_bfloat16*)(sm + H_HI + HPLANE + o2) = __float2bfloat16(c - __bfloat162float(h2));
        }

        const int b = (base + p) >> 16;
        const float gpx[3] = {c0, c0, c1};
        const float gpy[3] = {c1, c2, c2};
        float acc[16];
        #pragma unroll
        for (int j = 0; j < 16; j++) acc[j] = 0.0f;

        #pragma unroll
        for (int pl = 0; pl < 3; pl++) {
            float ix = (gpx[pl] + 1.0f) * 127.5f;
            float iy = (gpy[pl] + 1.0f) * 127.5f;
            float x0f = floorf(ix), y0f = floorf(iy);
            float fx = ix - x0f, fy = iy - y0f;
            int x0 = min(max((int)x0f, 0), RES - 2);
            int y0 = min(max((int)y0f, 0), RES - 2);
            float w00 = (1.0f - fx) * (1.0f - fy);
            float w10 = fx * (1.0f - fy);
            float w01 = (1.0f - fx) * fy;
            float w11 = fx * fy;
            const float* bp = g_tp + ((size_t)(b * 3 + pl) * (RES * RES) + y0 * RES + x0) * TD + q * 16;
            #pragma unroll
            for (int c = 0; c < 4; c++) {
                float4 v00 = *(const float4*)(bp + c * 4);
                float4 v10 = *(const float4*)(bp + TD + c * 4);
                float4 v01 = *(const float4*)(bp + RES * TD + c * 4);
                float4 v11 = *(const float4*)(bp + RES * TD + TD + c * 4);
                acc[c * 4 + 0] += w00 * v00.x + w10 * v10.x + w01 * v01.x + w11 * v11.x;
                acc[c * 4 + 1] += w00 * v00.y + w10 * v10.y + w01 * v01.y + w11 * v11.y;
                acc[c * 4 + 2] += w00 * v00.z + w10 * v10.z + w01 * v01.z + w11 * v11.z;
                acc[c * 4 + 3] += w00 * v00.w + w10 * v10.w + w01 * v01.w + w11 * v11.w;
            }
        }
        #pragma unroll
        for (int j = 0; j < 16; j++) {
            int k = CD + q * 16 + j;
            int off = (p * HSTR + k) * 2;
            __nv_bfloat16 h = __float2bfloat16(acc[j]);
            *(__nv_bfloat16*)(sm + H_HI + off)          = h;
            *(__nv_bfloat16*)(sm + H_HI + HPLANE + off) = __float2bfloat16(acc[j] - __bfloat162float(h));
        }
    }

    // per-thread fragment addresses
    const int rowM = warp * 16 + (lane & 15);
    const uint32_t aX = sb + X_HI + (uint32_t)((rowM * STRIDE + (lane >> 4) * 8) * 2);
    const uint32_t aH = sb + H_HI + (uint32_t)((rowM * HSTR + (lane >> 4) * 8) * 2);
    const uint32_t bOff4 = (uint32_t)((((lane & 7) + (lane >> 4) * 8) * STRIDE + ((lane >> 3) & 1) * 8) * 2);
    const uint32_t bOff2 = (uint32_t)(((lane & 7) * STRIDE + ((lane >> 3) & 1) * 8) * 2);
    const uint32_t bA4 = sb + W_A + bOff4, bB4 = sb + W_B + bOff4;
    const uint32_t bA2 = sb + W_A + bOff2;

    const int g   = lane >> 2;
    const int tig = lane & 3;
    const int pA  = warp * 16 + g;

    float D[16][4];
    float S[16][4];

    // L1: D = Win h
    CPA_WAIT(1);                       // w_in staged (w_skip may pend)
    __syncthreads();
    mma_layer16<5, HPLANE>(aH, bA4, D);
    CPA_WAIT(0);                       // w_skip staged
    __syncthreads();                   // all warps done reading W_A
    cpa_stage(sb + W_A, g_wp + 2 * WSLOT, WSLOT, tid); CPA_COMMIT();   // g2: w_b0

    // skip: S = Wskip h
    mma_layer16<5, HPLANE>(aH, bB4, S);
    __syncthreads();                   // all done reading H + W_B
    epi<false>(sm, D, S, bS + 0, nullptr, pA, tig);                    // x1 -> X (H now dead)
    cpa_stage(sb + W_B, g_wp + 3 * WSLOT, WSLOT, tid); CPA_COMMIT();   // g3: w_b1
    CPA_WAIT(1);                       // w_b0 staged
    __syncthreads();

    // L2: D = W0 x1
    mma_layer16<8, PLANE>(aX, bA4, D);
    __syncthreads();
    cpa_stage(sb + W_A, g_wp + 4 * WSLOT, WSLOT, tid); CPA_COMMIT();   // g4: w_a0
    epi<false>(sm, D, S, bS + 256, nullptr, pA, tig);                  // x2 -> X
    CPA_WAIT(1);                       // w_b1 staged
    __syncthreads();

    // L3: D = W1 x2 ; combine with skip S
    mma_layer16<8, PLANE>(aX, bB4, D);
    __syncthreads();
    cpa_stage(sb + W_B, g_wp + 5 * WSLOT, WSLOT, tid); CPA_COMMIT();   // g5: w_a1
    epi<true>(sm, D, S, bS + 384, bS + 128, pA, tig);                  // x4 -> X
    CPA_WAIT(1);                       // w_a0 staged
    __syncthreads();

    // L4: D = W2 x4
    mma_layer16<8, PLANE>(aX, bA4, D);
    __syncthreads();
    cpa_stage(sb + W_A, g_wp + 6 * WSLOT, 8 * ROWB, tid);              // g6: w_out hi
    cpa_stage(sb + W_A + PLANE, g_wp + 6 * WSLOT + 8 * ROWB, 8 * ROWB, tid);
    CPA_COMMIT();
    epi<false>(sm, D, S, bS + 512, nullptr, pA, tig);                  // x5 -> X
    CPA_WAIT(1);                       // w_a1 staged
    __syncthreads();

    // L5: D = W3 x5
    mma_layer16<8, PLANE>(aX, bB4, D);
    __syncthreads();
    epi<false>(sm, D, S, bS + 640, nullptr, pA, tig);                  // x6 -> X
    CPA_WAIT(0);                       // w_out staged
    __syncthreads();

    // L6: out = Wout x6 (single n-tile; cols 0..3 valid)
    float Do[4];
    mma_layer1<8>(aX, bA2, Do);

    // final epilogue
    {
        const int pB  = pA + 8;
        const int gpA = base + pA, gpB = base + pB;
        if (tig == 0) {
            float v0 = Do[0] + bS[768], v1 = Do[1] + bS[769];
            float v2 = Do[2] + bS[768], v3 = Do[3] + bS[769];
            out[gpA * 3 + 0] = 1.0f / (1.0f + expf(-v0));
            out[gpA * 3 + 1] = 1.0f / (1.0f + expf(-v1));
            out[gpB * 3 + 0] = 1.0f / (1.0f + expf(-v2));
            out[gpB * 3 + 1] = 1.0f / (1.0f + expf(-v3));
        } else if (tig == 1) {
            float v0 = Do[0] + bS[770], v1 = Do[1] + bS[771];
            float v2 = Do[2] + bS[770], v3 = Do[3] + bS[771];
            out[gpA * 3 + 2] = 1.0f / (1.0f + expf(-v0));
            out[gpB * 3 + 2] = 1.0f / (1.0f + expf(-v2));
            float a0 = cS[pA * 3 + 0], a1 = cS[pA * 3 + 1], a2 = cS[pA * 3 + 2];
            bool selA = (a0 > -1.0f) && (a0 < 1.0f) && (a1 > -1.0f) && (a1 < 1.0f) &&
                        (a2 > -1.0f) && (a2 < 1.0f);
            float b0 = cS[pB * 3 + 0], b1 = cS[pB * 3 + 1], b2 = cS[pB * 3 + 2];
            bool selB = (b0 > -1.0f) && (b0 < 1.0f) && (b1 > -1.0f) && (b1 < 1.0f) &&
                        (b2 > -1.0f) && (b2 < 1.0f);
            out[3 * NPTS + gpA] = selA ? expf(v1 - 1.0f) : 0.0f;
            out[3 * NPTS + gpB] = selB ? expf(v3 - 1.0f) : 0.0f;
        }
    }
}

// ---------------- launch ----------------
extern "C" void kernel_launch(void* const* d_in, const int* in_sizes, int n_in,
                              void* d_out, int out_size) {
    const float* triplane = (const float*)d_in[0];
    const float* coords   = (const float*)d_in[1];
    const float* w_in     = (const float*)d_in[2];
    const float* b_in     = (const float*)d_in[3];
    const float* w_skip   = (const float*)d_in[4];
    const float* b_skip   = (const float*)d_in[5];
    const float* w_before = (const float*)d_in[6];
    const float* b_before = (const float*)d_in[7];
    const float* w_after  = (const float*)d_in[8];
    const float* b_after  = (const float*)d_in[9];
    const float* w_out    = (const float*)d_in[10];
    const float* b_out    = (const float*)d_in[11];
    float* out = (float*)d_out;

    static bool attr_set = false;
    if (!attr_set) {
        cudaFuncSetAttribute(decoder_kernel,
                             cudaFuncAttributeMaxDynamicSharedMemorySize, SMEM_BYTES);
        attr_set = true;
    }

    tp_transpose_kernel<<<dim3(RES * RES / 128, 12), 256>>>(triplane);
    prep_w_kernel<<<(6 * 128 * STRIDE + 8 * STRIDE + 255) / 256, 256>>>(
        w_in, w_skip, w_before, w_after, w_out);
    decoder_kernel<<<NPTS / NP, NTHR, SMEM_BYTES>>>(
        coords, b_in, b_skip, b_before, b_after, b_out, out);
}

// round 5
// speedup vs baseline: 2.8565x; 1.0979x over previous
#include <cuda_runtime.h>
#include <cuda_bf16.h>
#include <math.h>
#include <stdint.h>

// ---------------- problem constants ----------------
#define BB     4
#define PP     65536
#define NPTS   (BB * PP)
#define TD     32
#define HID    128
#define CD     36
#define FIN    68
#define RES    256

#define NP     64               // points per CTA
#define NTHR   128              // 4 warps
#define STRIDE 136              // padded row stride (elems) for X and W
#define ROWB   (STRIDE * 2)     // 272 bytes per row
#define WPLANE (128 * ROWB)     // 34816: weight plane (128 neurons)
#define XPLANE (NP * ROWB)      // 17408: activation plane (64 points)
#define HSTR   88               // H row stride (elems), K range 0..79
#define HPLANE (NP * HSTR * 2)  // 11264

// smem layout (bytes). H aliases X (H dies before first X write).
#define X_HI      0             // X hi; lo at +XPLANE  (total 34816)
#define H_HI      0             // H hi; lo at +HPLANE  (total 22528, aliased)
#define W_0       34816         // single W buffer: hi, lo at +WPLANE (total 69632)
#define SM_BIAS   104448        // 772 floats
#define SM_COORD  107536        // 192 floats
#define SMEM_BYTES 108304

// ---------------- device scratch ----------------
__device__ __align__(16) float g_tp[12 * RES * RES * TD];
// slots 0=w_in 1=w_skip 2=w_b0 3=w_b1 4=w_a0 5=w_a1 (hi WPLANE + lo WPLANE), 6=w_out (hi 2176 + lo 2176)
#define WSLOT (2 * WPLANE)
__device__ __align__(16) unsigned char g_wp[6 * WSLOT + 2 * 8 * ROWB];

// ---------------- helpers ----------------
__device__ __forceinline__ uint32_t smem_u32(const void* p) {
    uint32_t a;
    asm("{ .reg .u64 t; cvta.to.shared.u64 t, %1; cvt.u32.u64 %0, t; }" : "=r"(a) : "l"(p));
    return a;
}
__device__ __forceinline__ uint32_t packbf(float lo, float hi) {
    uint32_t r;
    asm("cvt.rn.bf16x2.f32 %0, %1, %2;" : "=r"(r) : "f"(hi), "f"(lo));
    return r;
}
__device__ __forceinline__ float bfLow(uint32_t h)  { return __uint_as_float(h << 16); }
__device__ __forceinline__ float bfHigh(uint32_t h) { return __uint_as_float(h & 0xFFFF0000u); }

__device__ __forceinline__ void ldsm4(uint32_t a, uint32_t r[4]) {
    asm volatile("ldmatrix.sync.aligned.m8n8.x4.shared.b16 {%0,%1,%2,%3}, [%4];"
                 : "=r"(r[0]), "=r"(r[1]), "=r"(r[2]), "=r"(r[3]) : "r"(a));
}
__device__ __forceinline__ void ldsm2(uint32_t a, uint32_t r[2]) {
    asm volatile("ldmatrix.sync.aligned.m8n8.x2.shared.b16 {%0,%1}, [%2];"
                 : "=r"(r[0]), "=r"(r[1]) : "r"(a));
}
__device__ __forceinline__ void mma16816(float d[4], const uint32_t a[4], const uint32_t b[2]) {
    asm volatile("mma.sync.aligned.m16n8k16.row.col.f32.bf16.bf16.f32 "
                 "{%0,%1,%2,%3}, {%4,%5,%6,%7}, {%8,%9}, {%0,%1,%2,%3};"
                 : "+f"(d[0]), "+f"(d[1]), "+f"(d[2]), "+f"(d[3])
                 : "r"(a[0]), "r"(a[1]), "r"(a[2]), "r"(a[3]), "r"(b[0]), "r"(b[1]));
}

// cp.async
__device__ __forceinline__ void cpa_stage(uint32_t dst, const unsigned char* src, int bytes, int tid) {
    for (int i = tid * 16; i < bytes; i += NTHR * 16)
        asm volatile("cp.async.cg.shared.global [%0], [%1], 16;" :: "r"(dst + i), "l"(src + i) : "memory");
}
#define CPA_COMMIT()  asm volatile("cp.async.commit_group;" ::: "memory")
#define CPA_WAIT0()   asm volatile("cp.async.wait_group 0;" ::: "memory")

// ---------------- merged prep kernel ----------------
// blocks [0, 6144): triplane transpose.  blocks [6144, ...): weight split hi/lo.
#define TP_BLKS (12 * 512)
#define WP_TOT  (6 * 128 * STRIDE + 8 * STRIDE)   // 105536
__global__ void prep_all_kernel(const float* __restrict__ tri,
                                const float* __restrict__ w_in,
                                const float* __restrict__ w_skip,
                                const float* __restrict__ w_before,
                                const float* __restrict__ w_after,
                                const float* __restrict__ w_out) {
    __shared__ float t[32 * 129 + 4];
    const int blk = blockIdx.x;
    const int tid = threadIdx.x;
    if (blk < TP_BLKS) {
        const int n   = blk >> 9;
        const int hw0 = (blk & 511) * 128;
        const int c   = tid >> 3;
        const int h8  = tid & 7;
        const float* src = tri + (size_t)(n * 32 + c) * 65536 + hw0;
        #pragma unroll
        for (int i = 0; i < 4; i++) {
            int hw = i * 32 + h8 * 4;
            float4 v = *(const float4*)(src + hw);
            float* tr = t + c * 129 + hw;
            tr[0] = v.x; tr[1] = v.y; tr[2] = v.z; tr[3] = v.w;
        }
        __syncthreads();
        #pragma unroll
        for (int i = 0; i < 4; i++) {
            int e  = tid + 256 * i;
            int hw = e >> 3, c4 = e & 7;
            float4 v = make_float4(t[(4 * c4 + 0) * 129 + hw], t[(4 * c4 + 1) * 129 + hw],
                                   t[(4 * c4 + 2) * 129 + hw], t[(4 * c4 + 3) * 129 + hw]);
            *(float4*)(g_tp + ((size_t)n * 65536 + hw0 + hw) * 32 + c4 * 4) = v;
        }
        return;
    }
    int idx = (blk - TP_BLKS) * 256 + tid;
    if (idx >= WP_TOT) return;
    const int HN = 6 * 128 * STRIDE;
    int slot, o, k, planeB;
    size_t sbase;
    if (idx < HN) {
        slot = idx / (128 * STRIDE);
        int e = idx % (128 * STRIDE);
        o = e / STRIDE; k = e % STRIDE;
        sbase = (size_t)slot * WSLOT;
        planeB = WPLANE;
    } else {
        slot = 6;
        int e = idx - HN;
        o = e / STRIDE; k = e % STRIDE;
        sbase = (size_t)6 * WSLOT;
        planeB = 8 * ROWB;
    }
    float v = 0.0f;
    switch (slot) {
        case 0: if (k < FIN) v = w_in[o * FIN + k]; break;
        case 1: if (k < FIN) v = w_skip[o * FIN + k]; break;
        case 2: if (k < HID) v = w_before[o * HID + k]; break;
        case 3: if (k < HID) v = w_before[HID * HID + o * HID + k]; break;
        case 4: if (k < HID) v = w_after[o * HID + k]; break;
        case 5: if (k < HID) v = w_after[HID * HID + o * HID + k]; break;
        case 6: if (o < 4 && k < HID) v = w_out[o * HID + k]; break;
    }
    __nv_bfloat16 hi = __float2bfloat16(v);
    __nv_bfloat16 lo = __float2bfloat16(v - __bfloat162float(hi));
    size_t off = (size_t)(o * STRIDE + k) * 2;
    *(__nv_bfloat16*)(g_wp + sbase + off)          = hi;
    *(__nv_bfloat16*)(g_wp + sbase + planeB + off) = lo;
}

// ---------------- MMA layers ----------------
// 16 n-tiles; B lo plane at +WPLANE; A lo plane at +ALO.
template <int KS, int ALO>
__device__ __forceinline__ void mma_layer16(uint32_t aHi, uint32_t bHi4, float D[16][4]) {
    #pragma unroll
    for (int nt = 0; nt < 16; nt++) { D[nt][0] = 0.f; D[nt][1] = 0.f; D[nt][2] = 0.f; D[nt][3] = 0.f; }
    #pragma unroll
    for (int k = 0; k < KS; k++) {
        uint32_t Ah[4], Al[4];
        ldsm4(aHi + k * 32, Ah);
        ldsm4(aHi + ALO + k * 32, Al);
        #pragma unroll
        for (int nt = 0; nt < 16; nt += 2) {
            uint32_t Bh[4], Bl[4];
            ldsm4(bHi4 + nt * (8 * ROWB) + k * 32, Bh);
            ldsm4(bHi4 + WPLANE + nt * (8 * ROWB) + k * 32, Bl);
            mma16816(D[nt],     Ah, Bh);
            mma16816(D[nt],     Ah, Bl);
            mma16816(D[nt],     Al, Bh);
            mma16816(D[nt + 1], Ah, Bh + 2);
            mma16816(D[nt + 1], Ah, Bl + 2);
            mma16816(D[nt + 1], Al, Bh + 2);
        }
    }
}

// single n-tile (output layer); A lo at +XPLANE, B lo at +WPLANE
template <int KS>
__device__ __forceinline__ void mma_layer1(uint32_t aHi, uint32_t bHi2, float d[4]) {
    d[0] = d[1] = d[2] = d[3] = 0.f;
    #pragma unroll
    for (int k = 0; k < KS; k++) {
        uint32_t Ah[4], Al[4], Bh[2], Bl[2];
        ldsm4(aHi + k * 32, Ah);
        ldsm4(aHi + XPLANE + k * 32, Al);
        ldsm2(bHi2 + k * 32, Bh);
        ldsm2(bHi2 + WPLANE + k * 32, Bl);
        mma16816(d, Ah, Bh);
        mma16816(d, Ah, Bl);
        mma16816(d, Al, Bh);
    }
}

// epilogue: bias + relu (+ skip combine), bf16 hi/lo split, store into X (warp-private rows)
template <bool SK>
__device__ __forceinline__ void epi(unsigned char* sm, float D[16][4], float S[16][4],
                                    const float* bd, const float* bs, int pA, int tig) {
    const int rowA = pA * ROWB;
    const int rowB = rowA + 8 * ROWB;
    #pragma unroll
    for (int nt = 0; nt < 16; nt++) {
        int c0 = nt * 8 + 2 * tig;
        float b0 = bd[c0], b1 = bd[c0 + 1];
        float x0 = fmaxf(D[nt][0] + b0, 0.f), x1 = fmaxf(D[nt][1] + b1, 0.f);
        float x2 = fmaxf(D[nt][2] + b0, 0.f), x3 = fmaxf(D[nt][3] + b1, 0.f);
        if (SK) {
            float s0 = bs[c0], s1 = bs[c0 + 1];
            x0 += fmaxf(S[nt][0] + s0, 0.f); x1 += fmaxf(S[nt][1] + s1, 0.f);
            x2 += fmaxf(S[nt][2] + s0, 0.f); x3 += fmaxf(S[nt][3] + s1, 0.f);
        }
        uint32_t h0 = packbf(x0, x1), h1 = packbf(x2, x3);
        uint32_t l0 = packbf(x0 - bfLow(h0), x1 - bfHigh(h0));
        uint32_t l1 = packbf(x2 - bfLow(h1), x3 - bfHigh(h1));
        int off = c0 * 2;
        *(uint32_t*)(sm + X_HI + rowA + off)          = h0;
        *(uint32_t*)(sm + X_HI + XPLANE + rowA + off) = l0;
        *(uint32_t*)(sm + X_HI + rowB + off)          = h1;
        *(uint32_t*)(sm + X_HI + XPLANE + rowB + off) = l1;
    }
}

// ---------------- main decoder kernel ----------------
__global__ void __launch_bounds__(NTHR, 2)
decoder_kernel(const float* __restrict__ coords,
               const float* __restrict__ b_in,
               const float* __restrict__ b_skip,
               const float* __restrict__ b_before,
               const float* __restrict__ b_after,
               const float* __restrict__ b_out,
               float* __restrict__ out) {
    extern __shared__ unsigned char sm[];
    const uint32_t sb = smem_u32(sm);
    const int tid  = threadIdx.x;
    const int lane = tid & 31;
    const int warp = tid >> 5;
    const int base = blockIdx.x * NP;

    float* bS = (float*)(sm + SM_BIAS);
    float* cS = (float*)(sm + SM_COORD);

    // stage first weights immediately (overlaps with gather)
    cpa_stage(sb + W_0, g_wp + 0 * WSLOT, WSLOT, tid); CPA_COMMIT();

    // coords + biases
    for (int i = tid; i < NP * 3; i += NTHR) cS[i] = coords[base * 3 + i];
    for (int i = tid; i < 772; i += NTHR) {
        float v;
        if (i < 128)      v = b_in[i];
        else if (i < 256) v = b_skip[i - 128];
        else if (i < 512) v = b_before[i - 256];
        else if (i < 768) v = b_after[i - 512];
        else              v = b_out[i - 768];
        bS[i] = v;
    }
    // zero H pad cols 68..79 (hi+lo)
    {
        int p = tid >> 1, q = tid & 1;
        #pragma unroll
        for (int j = 0; j < 6; j++) {
            int k = FIN + q * 6 + j;
            int off = (p * HSTR + k) * 2;
            *(uint16_t*)(sm + H_HI + off)          = 0;
            *(uint16_t*)(sm + H_HI + HPLANE + off) = 0;
        }
    }
    __syncthreads();

    // ---- gather + freq encode -> H (bf16 hi/lo, stride 88) ----
    {
        const int p = tid >> 1;
        const int q = tid & 1;
        const float c0 = cS[p * 3 + 0];
        const float c1 = cS[p * 3 + 1];
        const float c2 = cS[p * 3 + 2];
        const float nrm[3] = {(c0 + 1.0f) * 0.5f, (c1 + 1.0f) * 0.5f, (c2 + 1.0f) * 0.5f};

        for (int a = q; a < 18; a += 2) {
            int d = a / 6;
            int k = a - 6 * d;
            float freq = 3.14159265358979f * (float)(1 << k);
            float s, c;
            sincosf(nrm[d] * freq, &s, &c);
            int k1 = d * 12 + k, k2 = d * 12 + 6 + k;
            int o1 = (p * HSTR + k1) * 2, o2 = (p * HSTR + k2) * 2;
            __nv_bfloat16 h1 = __float2bfloat16(s);
            __nv_bfloat16 h2 = __float2bfloat16(c);
            *(__nv_bfloat16*)(sm + H_HI + o1)          = h1;
            *(__nv_bfloat16*)(sm + H_HI + HPLANE + o1) = __float2bfloat16(s - __bfloat162float(h1));
            *(__nv_bfloat16*)(sm + H_HI + o2)          = h2;
            *(__nv_bfloat16*)(sm + H_HI + HPLANE + o2) = __float2bfloat16(c - __bfloat162float(h2));
        }

        const int b = (base + p) >> 16;
        const float gpx[3] = {c0, c0, c1};
        const float gpy[3] = {c1, c2, c2};
        float acc[16];
        #pragma unroll
        for (int j = 0; j < 16; j++) acc[j] = 0.0f;

        #pragma unroll
        for (int pl = 0; pl < 3; pl++) {
            float ix = (gpx[pl] + 1.0f) * 127.5f;
            float iy = (gpy[pl] + 1.0f) * 127.5f;
            float x0f = floorf(ix), y0f = floorf(iy);
            float fx = ix - x0f, fy = iy - y0f;
            int x0 = min(max((int)x0f, 0), RES - 2);
            int y0 = min(max((int)y0f, 0), RES - 2);
            float w00 = (1.0f - fx) * (1.0f - fy);
            float w10 = fx * (1.0f - fy);
            float w01 = (1.0f - fx) * fy;
            float w11 = fx * fy;
            const float* bp = g_tp + ((size_t)(b * 3 + pl) * (RES * RES) + y0 * RES + x0) * TD + q * 16;
            #pragma unroll
            for (int c = 0; c < 4; c++) {
                float4 v00 = *(const float4*)(bp + c * 4);
                float4 v10 = *(const float4*)(bp + TD + c * 4);
                float4 v01 = *(const float4*)(bp + RES * TD + c * 4);
                float4 v11 = *(const float4*)(bp + RES * TD + TD + c * 4);
                acc[c * 4 + 0] += w00 * v00.x + w10 * v10.x + w01 * v01.x + w11 * v11.x;
                acc[c * 4 + 1] += w00 * v00.y + w10 * v10.y + w01 * v01.y + w11 * v11.y;
                acc[c * 4 + 2] += w00 * v00.z + w10 * v10.z + w01 * v01.z + w11 * v11.z;
                acc[c * 4 + 3] += w00 * v00.w + w10 * v10.w + w01 * v01.w + w11 * v11.w;
            }
        }
        #pragma unroll
        for (int j = 0; j < 16; j++) {
            int k = CD + q * 16 + j;
            int off = (p * HSTR + k) * 2;
            __nv_bfloat16 h = __float2bfloat16(acc[j]);
            *(__nv_bfloat16*)(sm + H_HI + off)          = h;
            *(__nv_bfloat16*)(sm + H_HI + HPLANE + off) = __float2bfloat16(acc[j] - __bfloat162float(h));
        }
    }

    // per-thread fragment addresses
    const int rowM = warp * 16 + (lane & 15);
    const uint32_t aX = sb + X_HI + (uint32_t)((rowM * STRIDE + (lane >> 4) * 8) * 2);
    const uint32_t aH = sb + H_HI + (uint32_t)((rowM * HSTR + (lane >> 4) * 8) * 2);
    const uint32_t bW4 = sb + W_0 +
        (uint32_t)((((lane & 7) + (lane >> 4) * 8) * STRIDE + ((lane >> 3) & 1) * 8) * 2);
    const uint32_t bW2 = sb + W_0 +
        (uint32_t)(((lane & 7) * STRIDE + ((lane >> 3) & 1) * 8) * 2);

    const int g   = lane >> 2;
    const int tig = lane & 3;
    const int pA  = warp * 16 + g;

    float D[16][4];
    float S[16][4];

    // L1: D = Win h
    CPA_WAIT0();
    __syncthreads();
    mma_layer16<5, HPLANE>(aH, bW4, D);
    __syncthreads();
    cpa_stage(sb + W_0, g_wp + 1 * WSLOT, WSLOT, tid); CPA_COMMIT();   // w_skip
    CPA_WAIT0();
    __syncthreads();

    // skip: S = Wskip h  (H still live)
    mma_layer16<5, HPLANE>(aH, bW4, S);
    __syncthreads();
    cpa_stage(sb + W_0, g_wp + 2 * WSLOT, WSLOT, tid); CPA_COMMIT();   // w_b0
    epi<false>(sm, D, S, bS + 0, nullptr, pA, tig);                    // x1 -> X (H dead)
    CPA_WAIT0();
    __syncthreads();

    // L2: D = W0 x1
    mma_layer16<8, XPLANE>(aX, bW4, D);
    __syncthreads();
    cpa_stage(sb + W_0, g_wp + 3 * WSLOT, WSLOT, tid); CPA_COMMIT();   // w_b1
    epi<false>(sm, D, S, bS + 256, nullptr, pA, tig);                  // x2 -> X
    CPA_WAIT0();
    __syncthreads();

    // L3: D = W1 x2 ; combine with skip S
    mma_layer16<8, XPLANE>(aX, bW4, D);
    __syncthreads();
    cpa_stage(sb + W_0, g_wp + 4 * WSLOT, WSLOT, tid); CPA_COMMIT();   // w_a0
    epi<true>(sm, D, S, bS + 384, bS + 128, pA, tig);                  // x4 -> X
    CPA_WAIT0();
    __syncthreads();

    // L4: D = W2 x4
    mma_layer16<8, XPLANE>(aX, bW4, D);
    __syncthreads();
    cpa_stage(sb + W_0, g_wp + 5 * WSLOT, WSLOT, tid); CPA_COMMIT();   // w_a1
    epi<false>(sm, D, S, bS + 512, nullptr, pA, tig);                  // x5 -> X
    CPA_WAIT0();
    __syncthreads();

    // L5: D = W3 x5
    mma_layer16<8, XPLANE>(aX, bW4, D);
    __syncthreads();
    cpa_stage(sb + W_0, g_wp + 6 * WSLOT, 8 * ROWB, tid);              // w_out hi
    cpa_stage(sb + W_0 + WPLANE, g_wp + 6 * WSLOT + 8 * ROWB, 8 * ROWB, tid); // w_out lo
    CPA_COMMIT();
    epi<false>(sm, D, S, bS + 640, nullptr, pA, tig);                  // x6 -> X
    CPA_WAIT0();
    __syncthreads();

    // L6: out = Wout x6 (single n-tile; cols 0..3 valid)
    float Do[4];
    mma_layer1<8>(aX, bW2, Do);

    // final epilogue
    {
        const int pB  = pA + 8;
        const int gpA = base + pA, gpB = base + pB;
        if (tig == 0) {
            float v0 = Do[0] + bS[768], v1 = Do[1] + bS[769];
            float v2 = Do[2] + bS[768], v3 = Do[3] + bS[769];
            out[gpA * 3 + 0] = 1.0f / (1.0f + expf(-v0));
            out[gpA * 3 + 1] = 1.0f / (1.0f + expf(-v1));
            out[gpB * 3 + 0] = 1.0f / (1.0f + expf(-v2));
            out[gpB * 3 + 1] = 1.0f / (1.0f + expf(-v3));
        } else if (tig == 1) {
            float v0 = Do[0] + bS[770], v1 = Do[1] + bS[771];
            float v2 = Do[2] + bS[770], v3 = Do[3] + bS[771];
            out[gpA * 3 + 2] = 1.0f / (1.0f + expf(-v0));
            out[gpB * 3 + 2] = 1.0f / (1.0f + expf(-v2));
            float a0 = cS[pA * 3 + 0], a1 = cS[pA * 3 + 1], a2 = cS[pA * 3 + 2];
            bool selA = (a0 > -1.0f) && (a0 < 1.0f) && (a1 > -1.0f) && (a1 < 1.0f) &&
                        (a2 > -1.0f) && (a2 < 1.0f);
            float b0 = cS[pB * 3 + 0], b1 = cS[pB * 3 + 1], b2 = cS[pB * 3 + 2];
            bool selB = (b0 > -1.0f) && (b0 < 1.0f) && (b1 > -1.0f) && (b1 < 1.0f) &&
                        (b2 > -1.0f) && (b2 < 1.0f);
            out[3 * NPTS + gpA] = selA ? expf(v1 - 1.0f) : 0.0f;
            out[3 * NPTS + gpB] = selB ? expf(v3 - 1.0f) : 0.0f;
        }
    }
}

// ---------------- launch ----------------
extern "C" void kernel_launch(void* const* d_in, const int* in_sizes, int n_in,
                              void* d_out, int out_size) {
    const float* triplane = (const float*)d_in[0];
    const float* coords   = (const float*)d_in[1];
    const float* w_in     = (const float*)d_in[2];
    const float* b_in     = (const float*)d_in[3];
    const float* w_skip   = (const float*)d_in[4];
    const float* b_skip   = (const float*)d_in[5];
    const float* w_before = (const float*)d_in[6];
    const float* b_before = (const float*)d_in[7];
    const float* w_after  = (const float*)d_in[8];
    const float* b_after  = (const float*)d_in[9];
    const float* w_out    = (const float*)d_in[10];
    const float* b_out    = (const float*)d_in[11];
    float* out = (float*)d_out;

    static bool attr_set = false;
    if (!attr_set) {
        cudaFuncSetAttribute(decoder_kernel,
                             cudaFuncAttributeMaxDynamicSharedMemorySize, SMEM_BYTES);
        attr_set = true;
    }

    const int wp_blks = (WP_TOT + 255) / 256;
    prep_all_kernel<<<TP_BLKS + wp_blks, 256>>>(
        triplane, w_in, w_skip, w_before, w_after, w_out);
    decoder_kernel<<<NPTS / NP, NTHR, SMEM_BYTES>>>(
        coords, b_in, b_skip, b_before, b_after, b_out, out);
}

// round 6
// speedup vs baseline: 3.2578x; 1.1405x over previous
#include <cuda_runtime.h>
#include <cuda_bf16.h>
#include <math.h>
#include <stdint.h>

// ---------------- problem constants ----------------
#define BB     4
#define PP     65536
#define NPTS   (BB * PP)
#define TD     32
#define HID    128
#define CD     36
#define FIN    68
#define RES    256

#define NP     64               // points per CTA
#define NTHR   256              // 8 warps: warp&3 = m-tile, warp>>2 = n-half
#define STRIDE 136              // padded row stride (elems) for X and W
#define ROWB   (STRIDE * 2)     // 272 bytes per row
#define WPLANE (128 * ROWB)     // 34816: weight plane (128 neurons)
#define XPLANE (NP * ROWB)      // 17408: activation plane (64 points)
#define HSTR   88               // H row stride (elems), K range 0..79
#define HPLANE (NP * HSTR * 2)  // 11264

// smem layout (bytes). H aliases X (H dies before first X write).
#define X_HI      0             // X hi; lo at +XPLANE  (total 34816)
#define H_HI      0             // H hi; lo at +HPLANE  (total 22528, aliased)
#define W_0       34816         // single W buffer: hi, lo at +WPLANE (total 69632)
#define SM_BIAS   104448        // 772 floats
#define SM_COORD  107536        // 192 floats
#define SMEM_BYTES 108304

// ---------------- device scratch ----------------
__device__ __align__(16) float g_tp[12 * RES * RES * TD];
#define WSLOT (2 * WPLANE)
__device__ __align__(16) unsigned char g_wp[6 * WSLOT + 2 * 8 * ROWB];

// ---------------- helpers ----------------
__device__ __forceinline__ uint32_t smem_u32(const void* p) {
    uint32_t a;
    asm("{ .reg .u64 t; cvta.to.shared.u64 t, %1; cvt.u32.u64 %0, t; }" : "=r"(a) : "l"(p));
    return a;
}
__device__ __forceinline__ uint32_t packbf(float lo, float hi) {
    uint32_t r;
    asm("cvt.rn.bf16x2.f32 %0, %1, %2;" : "=r"(r) : "f"(hi), "f"(lo));
    return r;
}
__device__ __forceinline__ float bfLow(uint32_t h)  { return __uint_as_float(h << 16); }
__device__ __forceinline__ float bfHigh(uint32_t h) { return __uint_as_float(h & 0xFFFF0000u); }

__device__ __forceinline__ void ldsm4(uint32_t a, uint32_t r[4]) {
    asm volatile("ldmatrix.sync.aligned.m8n8.x4.shared.b16 {%0,%1,%2,%3}, [%4];"
                 : "=r"(r[0]), "=r"(r[1]), "=r"(r[2]), "=r"(r[3]) : "r"(a));
}
__device__ __forceinline__ void ldsm2(uint32_t a, uint32_t r[2]) {
    asm volatile("ldmatrix.sync.aligned.m8n8.x2.shared.b16 {%0,%1}, [%2];"
                 : "=r"(r[0]), "=r"(r[1]) : "r"(a));
}
__device__ __forceinline__ void mma16816(float d[4], const uint32_t a[4], const uint32_t b[2]) {
    asm volatile("mma.sync.aligned.m16n8k16.row.col.f32.bf16.bf16.f32 "
                 "{%0,%1,%2,%3}, {%4,%5,%6,%7}, {%8,%9}, {%0,%1,%2,%3};"
                 : "+f"(d[0]), "+f"(d[1]), "+f"(d[2]), "+f"(d[3])
                 : "r"(a[0]), "r"(a[1]), "r"(a[2]), "r"(a[3]), "r"(b[0]), "r"(b[1]));
}

// cp.async
__device__ __forceinline__ void cpa_stage(uint32_t dst, const unsigned char* src, int bytes, int tid) {
    for (int i = tid * 16; i < bytes; i += NTHR * 16)
        asm volatile("cp.async.cg.shared.global [%0], [%1], 16;" :: "r"(dst + i), "l"(src + i) : "memory");
}
#define CPA_COMMIT()  asm volatile("cp.async.commit_group;" ::: "memory")
#define CPA_WAIT0()   asm volatile("cp.async.wait_group 0;" ::: "memory")

// ---------------- merged prep kernel ----------------
#define TP_BLKS (12 * 512)
#define WP_TOT  (6 * 128 * STRIDE + 8 * STRIDE)
__global__ void prep_all_kernel(const float* __restrict__ tri,
                                const float* __restrict__ w_in,
                                const float* __restrict__ w_skip,
                                const float* __restrict__ w_before,
                                const float* __restrict__ w_after,
                                const float* __restrict__ w_out) {
    __shared__ float t[32 * 129 + 4];
    const int blk = blockIdx.x;
    const int tid = threadIdx.x;
    if (blk < TP_BLKS) {
        const int n   = blk >> 9;
        const int hw0 = (blk & 511) * 128;
        const int c   = tid >> 3;
        const int h8  = tid & 7;
        const float* src = tri + (size_t)(n * 32 + c) * 65536 + hw0;
        #pragma unroll
        for (int i = 0; i < 4; i++) {
            int hw = i * 32 + h8 * 4;
            float4 v = *(const float4*)(src + hw);
            float* tr = t + c * 129 + hw;
            tr[0] = v.x; tr[1] = v.y; tr[2] = v.z; tr[3] = v.w;
        }
        __syncthreads();
        #pragma unroll
        for (int i = 0; i < 4; i++) {
            int e  = tid + 256 * i;
            int hw = e >> 3, c4 = e & 7;
            float4 v = make_float4(t[(4 * c4 + 0) * 129 + hw], t[(4 * c4 + 1) * 129 + hw],
                                   t[(4 * c4 + 2) * 129 + hw], t[(4 * c4 + 3) * 129 + hw]);
            *(float4*)(g_tp + ((size_t)n * 65536 + hw0 + hw) * 32 + c4 * 4) = v;
        }
        return;
    }
    int idx = (blk - TP_BLKS) * 256 + tid;
    if (idx >= WP_TOT) return;
    const int HN = 6 * 128 * STRIDE;
    int slot, o, k, planeB;
    size_t sbase;
    if (idx < HN) {
        slot = idx / (128 * STRIDE);
        int e = idx % (128 * STRIDE);
        o = e / STRIDE; k = e % STRIDE;
        sbase = (size_t)slot * WSLOT;
        planeB = WPLANE;
    } else {
        slot = 6;
        int e = idx - HN;
        o = e / STRIDE; k = e % STRIDE;
        sbase = (size_t)6 * WSLOT;
        planeB = 8 * ROWB;
    }
    float v = 0.0f;
    switch (slot) {
        case 0: if (k < FIN) v = w_in[o * FIN + k]; break;
        case 1: if (k < FIN) v = w_skip[o * FIN + k]; break;
        case 2: if (k < HID) v = w_before[o * HID + k]; break;
        case 3: if (k < HID) v = w_before[HID * HID + o * HID + k]; break;
        case 4: if (k < HID) v = w_after[o * HID + k]; break;
        case 5: if (k < HID) v = w_after[HID * HID + o * HID + k]; break;
        case 6: if (o < 4 && k < HID) v = w_out[o * HID + k]; break;
    }
    __nv_bfloat16 hi = __float2bfloat16(v);
    __nv_bfloat16 lo = __float2bfloat16(v - __bfloat162float(hi));
    size_t off = (size_t)(o * STRIDE + k) * 2;
    *(__nv_bfloat16*)(g_wp + sbase + off)          = hi;
    *(__nv_bfloat16*)(g_wp + sbase + planeB + off) = lo;
}

// ---------------- MMA layers ----------------
// 8 n-tiles (this warp's 64-neuron half); B lo plane at +WPLANE; A lo at +ALO.
template <int KS, int ALO>
__device__ __forceinline__ void mma_layer8(uint32_t aHi, uint32_t bHi4, float D[8][4]) {
    #pragma unroll
    for (int nt = 0; nt < 8; nt++) { D[nt][0] = 0.f; D[nt][1] = 0.f; D[nt][2] = 0.f; D[nt][3] = 0.f; }
    #pragma unroll
    for (int k = 0; k < KS; k++) {
        uint32_t Ah[4], Al[4];
        ldsm4(aHi + k * 32, Ah);
        ldsm4(aHi + ALO + k * 32, Al);
        #pragma unroll
        for (int nt = 0; nt < 8; nt += 2) {
            uint32_t Bh[4], Bl[4];
            ldsm4(bHi4 + nt * (8 * ROWB) + k * 32, Bh);
            ldsm4(bHi4 + WPLANE + nt * (8 * ROWB) + k * 32, Bl);
            mma16816(D[nt],     Ah, Bh);
            mma16816(D[nt],     Ah, Bl);
            mma16816(D[nt],     Al, Bh);
            mma16816(D[nt + 1], Ah, Bh + 2);
            mma16816(D[nt + 1], Ah, Bl + 2);
            mma16816(D[nt + 1], Al, Bh + 2);
        }
    }
}

// single n-tile (output layer); A lo at +XPLANE, B lo at +WPLANE
template <int KS>
__device__ __forceinline__ void mma_layer1(uint32_t aHi, uint32_t bHi2, float d[4]) {
    d[0] = d[1] = d[2] = d[3] = 0.f;
    #pragma unroll
    for (int k = 0; k < KS; k++) {
        uint32_t Ah[4], Al[4], Bh[2], Bl[2];
        ldsm4(aHi + k * 32, Ah);
        ldsm4(aHi + XPLANE + k * 32, Al);
        ldsm2(bHi2 + k * 32, Bh);
        ldsm2(bHi2 + WPLANE + k * 32, Bl);
        mma16816(d, Ah, Bh);
        mma16816(d, Ah, Bl);
        mma16816(d, Al, Bh);
    }
}

// epilogue: bias + relu (+ skip), bf16 hi/lo split, store into X (warp-private rows/cols).
// bd/bs already offset by this warp's 64-neuron half; colb = n-half * 64.
template <bool SK>
__device__ __forceinline__ void epi(unsigned char* sm, float D[8][4], float S[8][4],
                                    const float* bd, const float* bs,
                                    int pA, int tig, int colb) {
    const int rowA = pA * ROWB;
    const int rowB = rowA + 8 * ROWB;
    #pragma unroll
    for (int nt = 0; nt < 8; nt++) {
        int c0 = nt * 8 + 2 * tig;
        float b0 = bd[c0], b1 = bd[c0 + 1];
        float x0 = fmaxf(D[nt][0] + b0, 0.f), x1 = fmaxf(D[nt][1] + b1, 0.f);
        float x2 = fmaxf(D[nt][2] + b0, 0.f), x3 = fmaxf(D[nt][3] + b1, 0.f);
        if (SK) {
            float s0 = bs[c0], s1 = bs[c0 + 1];
            x0 += fmaxf(S[nt][0] + s0, 0.f); x1 += fmaxf(S[nt][1] + s1, 0.f);
            x2 += fmaxf(S[nt][2] + s0, 0.f); x3 += fmaxf(S[nt][3] + s1, 0.f);
        }
        uint32_t h0 = packbf(x0, x1), h1 = packbf(x2, x3);
        uint32_t l0 = packbf(x0 - bfLow(h0), x1 - bfHigh(h0));
        uint32_t l1 = packbf(x2 - bfLow(h1), x3 - bfHigh(h1));
        int off = (colb + c0) * 2;
        *(uint32_t*)(sm + X_HI + rowA + off)          = h0;
        *(uint32_t*)(sm + X_HI + XPLANE + rowA + off) = l0;
        *(uint32_t*)(sm + X_HI + rowB + off)          = h1;
        *(uint32_t*)(sm + X_HI + XPLANE + rowB + off) = l1;
    }
}

// ---------------- main decoder kernel ----------------
__global__ void __launch_bounds__(NTHR, 2)
decoder_kernel(const float* __restrict__ coords,
               const float* __restrict__ b_in,
               const float* __restrict__ b_skip,
               const float* __restrict__ b_before,
               const float* __restrict__ b_after,
               const float* __restrict__ b_out,
               float* __restrict__ out) {
    extern __shared__ unsigned char sm[];
    const uint32_t sb = smem_u32(sm);
    const int tid  = threadIdx.x;
    const int lane = tid & 31;
    const int warp = tid >> 5;
    const int mt   = warp & 3;      // m-tile 0..3
    const int nh   = warp >> 2;     // n-half 0..1
    const int base = blockIdx.x * NP;

    float* bS = (float*)(sm + SM_BIAS);
    float* cS = (float*)(sm + SM_COORD);

    // stage first weights immediately (overlaps with gather)
    cpa_stage(sb + W_0, g_wp + 0 * WSLOT, WSLOT, tid); CPA_COMMIT();

    // coords + biases
    for (int i = tid; i < NP * 3; i += NTHR) cS[i] = coords[base * 3 + i];
    for (int i = tid; i < 772; i += NTHR) {
        float v;
        if (i < 128)      v = b_in[i];
        else if (i < 256) v = b_skip[i - 128];
        else if (i < 512) v = b_before[i - 256];
        else if (i < 768) v = b_after[i - 512];
        else              v = b_out[i - 768];
        bS[i] = v;
    }
    // zero H pad cols 68..79 (hi+lo): 64 rows x 12 cols, 4 threads/row
    {
        int p = tid >> 2, q = tid & 3;
        #pragma unroll
        for (int j = 0; j < 3; j++) {
            int k = FIN + q * 3 + j;
            int off = (p * HSTR + k) * 2;
            *(uint16_t*)(sm + H_HI + off)          = 0;
            *(uint16_t*)(sm + H_HI + HPLANE + off) = 0;
        }
    }
    __syncthreads();

    // ---- gather + freq encode -> H (bf16 hi/lo, stride 88): 4 threads/point ----
    {
        const int p = tid >> 2;
        const int q = tid & 3;
        const float c0 = cS[p * 3 + 0];
        const float c1 = cS[p * 3 + 1];
        const float c2 = cS[p * 3 + 2];
        const float nrm[3] = {(c0 + 1.0f) * 0.5f, (c1 + 1.0f) * 0.5f, (c2 + 1.0f) * 0.5f};

        for (int a = q; a < 18; a += 4) {
            int d = a / 6;
            int k = a - 6 * d;
            float freq = 3.14159265358979f * (float)(1 << k);
            float s, c;
            sincosf(nrm[d] * freq, &s, &c);
            int k1 = d * 12 + k, k2 = d * 12 + 6 + k;
            int o1 = (p * HSTR + k1) * 2, o2 = (p * HSTR + k2) * 2;
            __nv_bfloat16 h1 = __float2bfloat16(s);
            __nv_bfloat16 h2 = __float2bfloat16(c);
            *(__nv_bfloat16*)(sm + H_HI + o1)          = h1;
            *(__nv_bfloat16*)(sm + H_HI + HPLANE + o1) = __float2bfloat16(s - __bfloat162float(h1));
            *(__nv_bfloat16*)(sm + H_HI + o2)          = h2;
            *(__nv_bfloat16*)(sm + H_HI + HPLANE + o2) = __float2bfloat16(c - __bfloat162float(h2));
        }

        const int b = (base + p) >> 16;
        const float gpx[3] = {c0, c0, c1};
        const float gpy[3] = {c1, c2, c2};
        float acc[8];
        #pragma unroll
        for (int j = 0; j < 8; j++) acc[j] = 0.0f;

        #pragma unroll
        for (int pl = 0; pl < 3; pl++) {
            float ix = (gpx[pl] + 1.0f) * 127.5f;
            float iy = (gpy[pl] + 1.0f) * 127.5f;
            float x0f = floorf(ix), y0f = floorf(iy);
            float fx = ix - x0f, fy = iy - y0f;
            int x0 = min(max((int)x0f, 0), RES - 2);
            int y0 = min(max((int)y0f, 0), RES - 2);
            float w00 = (1.0f - fx) * (1.0f - fy);
            float w10 = fx * (1.0f - fy);
            float w01 = (1.0f - fx) * fy;
            float w11 = fx * fy;
            const float* bp = g_tp + ((size_t)(b * 3 + pl) * (RES * RES) + y0 * RES + x0) * TD + q * 8;
            #pragma unroll
            for (int c = 0; c < 2; c++) {
                float4 v00 = *(const float4*)(bp + c * 4);
                float4 v10 = *(const float4*)(bp + TD + c * 4);
                float4 v01 = *(const float4*)(bp + RES * TD + c * 4);
                float4 v11 = *(const float4*)(bp + RES * TD + TD + c * 4);
                acc[c * 4 + 0] += w00 * v00.x + w10 * v10.x + w01 * v01.x + w11 * v11.x;
                acc[c * 4 + 1] += w00 * v00.y + w10 * v10.y + w01 * v01.y + w11 * v11.y;
                acc[c * 4 + 2] += w00 * v00.z + w10 * v10.z + w01 * v01.z + w11 * v11.z;
                acc[c * 4 + 3] += w00 * v00.w + w10 * v10.w + w01 * v01.w + w11 * v11.w;
            }
        }
        #pragma unroll
        for (int j = 0; j < 8; j++) {
            int k = CD + q * 8 + j;
            int off = (p * HSTR + k) * 2;
            __nv_bfloat16 h = __float2bfloat16(acc[j]);
            *(__nv_bfloat16*)(sm + H_HI + off)          = h;
            *(__nv_bfloat16*)(sm + H_HI + HPLANE + off) = __float2bfloat16(acc[j] - __bfloat162float(h));
        }
    }

    // per-thread fragment addresses
    const int rowM = mt * 16 + (lane & 15);
    const uint32_t aX = sb + X_HI + (uint32_t)((rowM * STRIDE + (lane >> 4) * 8) * 2);
    const uint32_t aH = sb + H_HI + (uint32_t)((rowM * HSTR + (lane >> 4) * 8) * 2);
    // B base: this warp's n-half starts at neuron nh*64 = n-tile nh*8
    const uint32_t bW4 = sb + W_0 + (uint32_t)(nh * 8 * (8 * ROWB)) +
        (uint32_t)((((lane & 7) + (lane >> 4) * 8) * STRIDE + ((lane >> 3) & 1) * 8) * 2);
    const uint32_t bW2 = sb + W_0 +
        (uint32_t)(((lane & 7) * STRIDE + ((lane >> 3) & 1) * 8) * 2);

    const int g    = lane >> 2;
    const int tig  = lane & 3;
    const int pA   = mt * 16 + g;
    const int colb = nh * 64;

    float D[8][4];
    float S[8][4];

    // L1: D = Win h
    CPA_WAIT0();
    __syncthreads();
    mma_layer8<5, HPLANE>(aH, bW4, D);
    __syncthreads();
    cpa_stage(sb + W_0, g_wp + 1 * WSLOT, WSLOT, tid); CPA_COMMIT();   // w_skip
    CPA_WAIT0();
    __syncthreads();

    // skip: S = Wskip h  (H still live)
    mma_layer8<5, HPLANE>(aH, bW4, S);
    __syncthreads();
    cpa_stage(sb + W_0, g_wp + 2 * WSLOT, WSLOT, tid); CPA_COMMIT();   // w_b0
    epi<false>(sm, D, S, bS + 0 + colb, nullptr, pA, tig, colb);       // x1 -> X (H dead)
    CPA_WAIT0();
    __syncthreads();

    // L2: D = W0 x1
    mma_layer8<8, XPLANE>(aX, bW4, D);
    __syncthreads();
    cpa_stage(sb + W_0, g_wp + 3 * WSLOT, WSLOT, tid); CPA_COMMIT();   // w_b1
    epi<false>(sm, D, S, bS + 256 + colb, nullptr, pA, tig, colb);     // x2 -> X
    CPA_WAIT0();
    __syncthreads();

    // L3: D = W1 x2 ; combine with skip S
    mma_layer8<8, XPLANE>(aX, bW4, D);
    __syncthreads();
    cpa_stage(sb + W_0, g_wp + 4 * WSLOT, WSLOT, tid); CPA_COMMIT();   // w_a0
    epi<true>(sm, D, S, bS + 384 + colb, bS + 128 + colb, pA, tig, colb); // x4 -> X
    CPA_WAIT0();
    __syncthreads();

    // L4: D = W2 x4
    mma_layer8<8, XPLANE>(aX, bW4, D);
    __syncthreads();
    cpa_stage(sb + W_0, g_wp + 5 * WSLOT, WSLOT, tid); CPA_COMMIT();   // w_a1
    epi<false>(sm, D, S, bS + 512 + colb, nullptr, pA, tig, colb);     // x5 -> X
    CPA_WAIT0();
    __syncthreads();

    // L5: D = W3 x5
    mma_layer8<8, XPLANE>(aX, bW4, D);
    __syncthreads();
    cpa_stage(sb + W_0, g_wp + 6 * WSLOT, 8 * ROWB, tid);              // w_out hi
    cpa_stage(sb + W_0 + WPLANE, g_wp + 6 * WSLOT + 8 * ROWB, 8 * ROWB, tid); // w_out lo
    CPA_COMMIT();
    epi<false>(sm, D, S, bS + 640 + colb, nullptr, pA, tig, colb);     // x6 -> X
    CPA_WAIT0();
    __syncthreads();

    // L6: out = Wout x6 (n-half 0 warps only; cols 0..3 valid)
    if (nh == 0) {
        float Do[4];
        mma_layer1<8>(aX, bW2, Do);
        const int pB  = pA + 8;
        const int gpA = base + pA, gpB = base + pB;
        if (tig == 0) {
            float v0 = Do[0] + bS[768], v1 = Do[1] + bS[769];
            float v2 = Do[2] + bS[768], v3 = Do[3] + bS[769];
            out[gpA * 3 + 0] = 1.0f / (1.0f + expf(-v0));
            out[gpA * 3 + 1] = 1.0f / (1.0f + expf(-v1));
            out[gpB * 3 + 0] = 1.0f / (1.0f + expf(-v2));
            out[gpB * 3 + 1] = 1.0f / (1.0f + expf(-v3));
        } else if (tig == 1) {
            float v0 = Do[0] + bS[770], v1 = Do[1] + bS[771];
            float v2 = Do[2] + bS[770], v3 = Do[3] + bS[771];
            out[gpA * 3 + 2] = 1.0f / (1.0f + expf(-v0));
            out[gpB * 3 + 2] = 1.0f / (1.0f + expf(-v2));
            float a0 = cS[pA * 3 + 0], a1 = cS[pA * 3 + 1], a2 = cS[pA * 3 + 2];
            bool selA = (a0 > -1.0f) && (a0 < 1.0f) && (a1 > -1.0f) && (a1 < 1.0f) &&
                        (a2 > -1.0f) && (a2 < 1.0f);
            float b0 = cS[pB * 3 + 0], b1 = cS[pB * 3 + 1], b2 = cS[pB * 3 + 2];
            bool selB = (b0 > -1.0f) && (b0 < 1.0f) && (b1 > -1.0f) && (b1 < 1.0f) &&
                        (b2 > -1.0f) && (b2 < 1.0f);
            out[3 * NPTS + gpA] = selA ? expf(v1 - 1.0f) : 0.0f;
            out[3 * NPTS + gpB] = selB ? expf(v3 - 1.0f) : 0.0f;
        }
    }
}

// ---------------- launch ----------------
extern "C" void kernel_launch(void* const* d_in, const int* in_sizes, int n_in,
                              void* d_out, int out_size) {
    const float* triplane = (const float*)d_in[0];
    const float* coords   = (const float*)d_in[1];
    const float* w_in     = (const float*)d_in[2];
    const float* b_in     = (const float*)d_in[3];
    const float* w_skip   = (const float*)d_in[4];
    const float* b_skip   = (const float*)d_in[5];
    const float* w_before = (const float*)d_in[6];
    const float* b_before = (const float*)d_in[7];
    const float* w_after  = (const float*)d_in[8];
    const float* b_after  = (const float*)d_in[9];
    const float* w_out    = (const float*)d_in[10];
    const float* b_out    = (const float*)d_in[11];
    float* out = (float*)d_out;

    static bool attr_set = false;
    if (!attr_set) {
        cudaFuncSetAttribute(decoder_kernel,
                             cudaFuncAttributeMaxDynamicSharedMemorySize, SMEM_BYTES);
        attr_set = true;
    }

    const int wp_blks = (WP_TOT + 255) / 256;
    prep_all_kernel<<<TP_BLKS + wp_blks, 256>>>(
        triplane, w_in, w_skip, w_before, w_after, w_out);
    decoder_kernel<<<NPTS / NP, NTHR, SMEM_BYTES>>>(
        coords, b_in, b_skip, b_before, b_after, b_out, out);
}

// round 7
// speedup vs baseline: 4.1362x; 1.2696x over previous
#include <cuda_runtime.h>
#include <cuda_fp16.h>
#include <math.h>
#include <stdint.h>

// ---------------- problem constants ----------------
#define BB     4
#define PP     65536
#define NPTS   (BB * PP)
#define TD     32
#define HID    128
#define CD     36
#define FIN    68
#define RES    256

#define NP     64               // points per CTA
#define NTHR   256              // 8 warps: warp&3 = m-tile, warp>>2 = n-half
#define STRIDE 136              // padded row stride (elems) for X and W
#define ROWB   (STRIDE * 2)     // 272 bytes per row
#define WPLANE (128 * ROWB)     // 34816: single fp16 weight plane (128 neurons)
#define XPLANE (NP * ROWB)      // 17408: activation plane (64 points)
#define HSTR   88               // H row stride (elems), K range 0..79
#define HPLANE (NP * HSTR * 2)  // 11264

// smem layout (bytes). H aliases X (H dies before first X write).
#define X_HI      0             // X hi; lo at +XPLANE  (total 34816)
#define H_HI      0             // H hi; lo at +HPLANE  (total 22528, aliased)
#define W_A       34816         // weight buffer A (single plane, 34816)
#define W_B       69632         // weight buffer B
#define SM_BIAS   104448        // 772 floats
#define SM_COORD  107536        // 192 floats
#define SMEM_BYTES 108304

// ---------------- device scratch ----------------
__device__ __align__(16) float g_tp[12 * RES * RES * TD];
// slots 0=w_in 1=w_skip 2=w_b0 3=w_b1 4=w_a0 5=w_a1 (WPLANE each, fp16), 6=w_out (8*ROWB)
__device__ __align__(16) unsigned char g_wp[6 * WPLANE + 8 * ROWB];

// ---------------- helpers ----------------
__device__ __forceinline__ uint32_t smem_u32(const void* p) {
    uint32_t a;
    asm("{ .reg .u64 t; cvta.to.shared.u64 t, %1; cvt.u32.u64 %0, t; }" : "=r"(a) : "l"(p));
    return a;
}
__device__ __forceinline__ void ldsm4(uint32_t a, uint32_t r[4]) {
    asm volatile("ldmatrix.sync.aligned.m8n8.x4.shared.b16 {%0,%1,%2,%3}, [%4];"
                 : "=r"(r[0]), "=r"(r[1]), "=r"(r[2]), "=r"(r[3]) : "r"(a));
}
__device__ __forceinline__ void ldsm2(uint32_t a, uint32_t r[2]) {
    asm volatile("ldmatrix.sync.aligned.m8n8.x2.shared.b16 {%0,%1}, [%2];"
                 : "=r"(r[0]), "=r"(r[1]) : "r"(a));
}
__device__ __forceinline__ void mma16816(float d[4], const uint32_t a[4], const uint32_t b[2]) {
    asm volatile("mma.sync.aligned.m16n8k16.row.col.f32.f16.f16.f32 "
                 "{%0,%1,%2,%3}, {%4,%5,%6,%7}, {%8,%9}, {%0,%1,%2,%3};"
                 : "+f"(d[0]), "+f"(d[1]), "+f"(d[2]), "+f"(d[3])
                 : "r"(a[0]), "r"(a[1]), "r"(a[2]), "r"(a[3]), "r"(b[0]), "r"(b[1]));
}

// cp.async
__device__ __forceinline__ void cpa_stage(uint32_t dst, const unsigned char* src, int bytes, int tid) {
    for (int i = tid * 16; i < bytes; i += NTHR * 16)
        asm volatile("cp.async.cg.shared.global [%0], [%1], 16;" :: "r"(dst + i), "l"(src + i) : "memory");
}
#define CPA_COMMIT()  asm volatile("cp.async.commit_group;" ::: "memory")
#define CPA_WAIT0()   asm volatile("cp.async.wait_group 0;" ::: "memory")
#define CPA_WAIT1()   asm volatile("cp.async.wait_group 1;" ::: "memory")

// fp16 hi/lo split of an fp32 value
__device__ __forceinline__ void h2split(float x0, float x1, uint32_t& hp, uint32_t& lp) {
    __half2 h = __floats2half2_rn(x0, x1);
    float r0 = x0 - __low2float(h);
    float r1 = x1 - __high2float(h);
    __half2 l = __floats2half2_rn(r0, r1);
    hp = *(uint32_t*)&h;
    lp = *(uint32_t*)&l;
}

// ---------------- merged prep kernel ----------------
#define TP_BLKS (12 * 512)
#define WP_TOT  (6 * 128 * STRIDE + 8 * STRIDE)
__global__ void prep_all_kernel(const float* __restrict__ tri,
                                const float* __restrict__ w_in,
                                const float* __restrict__ w_skip,
                                const float* __restrict__ w_before,
                                const float* __restrict__ w_after,
                                const float* __restrict__ w_out) {
    __shared__ float t[32 * 129 + 4];
    const int blk = blockIdx.x;
    const int tid = threadIdx.x;
    if (blk < TP_BLKS) {
        const int n   = blk >> 9;
        const int hw0 = (blk & 511) * 128;
        const int c   = tid >> 3;
        const int h8  = tid & 7;
        const float* src = tri + (size_t)(n * 32 + c) * 65536 + hw0;
        #pragma unroll
        for (int i = 0; i < 4; i++) {
            int hw = i * 32 + h8 * 4;
            float4 v = *(const float4*)(src + hw);
            float* tr = t + c * 129 + hw;
            tr[0] = v.x; tr[1] = v.y; tr[2] = v.z; tr[3] = v.w;
        }
        __syncthreads();
        #pragma unroll
        for (int i = 0; i < 4; i++) {
            int e  = tid + 256 * i;
            int hw = e >> 3, c4 = e & 7;
            float4 v = make_float4(t[(4 * c4 + 0) * 129 + hw], t[(4 * c4 + 1) * 129 + hw],
                                   t[(4 * c4 + 2) * 129 + hw], t[(4 * c4 + 3) * 129 + hw]);
            *(float4*)(g_tp + ((size_t)n * 65536 + hw0 + hw) * 32 + c4 * 4) = v;
        }
        return;
    }
    int idx = (blk - TP_BLKS) * 256 + tid;
    if (idx >= WP_TOT) return;
    const int HN = 6 * 128 * STRIDE;
    int slot, o, k;
    size_t sbase;
    if (idx < HN) {
        slot = idx / (128 * STRIDE);
        int e = idx % (128 * STRIDE);
        o = e / STRIDE; k = e % STRIDE;
        sbase = (size_t)slot * WPLANE;
    } else {
        slot = 6;
        int e = idx - HN;
        o = e / STRIDE; k = e % STRIDE;
        sbase = (size_t)6 * WPLANE;
    }
    float v = 0.0f;
    switch (slot) {
        case 0: if (k < FIN) v = w_in[o * FIN + k]; break;
        case 1: if (k < FIN) v = w_skip[o * FIN + k]; break;
        case 2: if (k < HID) v = w_before[o * HID + k]; break;
        case 3: if (k < HID) v = w_before[HID * HID + o * HID + k]; break;
        case 4: if (k < HID) v = w_after[o * HID + k]; break;
        case 5: if (k < HID) v = w_after[HID * HID + o * HID + k]; break;
        case 6: if (o < 4 && k < HID) v = w_out[o * HID + k]; break;
    }
    *(__half*)(g_wp + sbase + (size_t)(o * STRIDE + k) * 2) = __float2half_rn(v);
}

// ---------------- MMA layers ----------------
// 8 n-tiles (this warp's 64-neuron half); B single plane; A hi + lo at +ALO.
// D = (Ah + Al) * B  — 4 mma per nt-pair per k.
template <int KS, int ALO>
__device__ __forceinline__ void mma_layer8(uint32_t aHi, uint32_t bB4, float D[8][4]) {
    #pragma unroll
    for (int nt = 0; nt < 8; nt++) { D[nt][0] = 0.f; D[nt][1] = 0.f; D[nt][2] = 0.f; D[nt][3] = 0.f; }
    #pragma unroll
    for (int k = 0; k < KS; k++) {
        uint32_t Ah[4], Al[4];
        ldsm4(aHi + k * 32, Ah);
        ldsm4(aHi + ALO + k * 32, Al);
        #pragma unroll
        for (int nt = 0; nt < 8; nt += 2) {
            uint32_t Bh[4];
            ldsm4(bB4 + nt * (8 * ROWB) + k * 32, Bh);
            mma16816(D[nt],     Ah, Bh);
            mma16816(D[nt],     Al, Bh);
            mma16816(D[nt + 1], Ah, Bh + 2);
            mma16816(D[nt + 1], Al, Bh + 2);
        }
    }
}

// single n-tile (output layer); A lo at +XPLANE
template <int KS>
__device__ __forceinline__ void mma_layer1(uint32_t aHi, uint32_t bB2, float d[4]) {
    d[0] = d[1] = d[2] = d[3] = 0.f;
    #pragma unroll
    for (int k = 0; k < KS; k++) {
        uint32_t Ah[4], Al[4], Bh[2];
        ldsm4(aHi + k * 32, Ah);
        ldsm4(aHi + XPLANE + k * 32, Al);
        ldsm2(bB2 + k * 32, Bh);
        mma16816(d, Ah, Bh);
        mma16816(d, Al, Bh);
    }
}

// epilogue: bias + relu (+ skip), fp16 hi/lo split, store into X (warp-private rows/cols).
template <bool SK>
__device__ __forceinline__ void epi(unsigned char* sm, float D[8][4], float S[8][4],
                                    const float* bd, const float* bs,
                                    int pA, int tig, int colb) {
    const int rowA = pA * ROWB;
    const int rowB = rowA + 8 * ROWB;
    #pragma unroll
    for (int nt = 0; nt < 8; nt++) {
        int c0 = nt * 8 + 2 * tig;
        float b0 = bd[c0], b1 = bd[c0 + 1];
        float x0 = fmaxf(D[nt][0] + b0, 0.f), x1 = fmaxf(D[nt][1] + b1, 0.f);
        float x2 = fmaxf(D[nt][2] + b0, 0.f), x3 = fmaxf(D[nt][3] + b1, 0.f);
        if (SK) {
            float s0 = bs[c0], s1 = bs[c0 + 1];
            x0 += fmaxf(S[nt][0] + s0, 0.f); x1 += fmaxf(S[nt][1] + s1, 0.f);
            x2 += fmaxf(S[nt][2] + s0, 0.f); x3 += fmaxf(S[nt][3] + s1, 0.f);
        }
        uint32_t h0, l0, h1, l1;
        h2split(x0, x1, h0, l0);
        h2split(x2, x3, h1, l1);
        int off = (colb + c0) * 2;
        *(uint32_t*)(sm + X_HI + rowA + off)          = h0;
        *(uint32_t*)(sm + X_HI + XPLANE + rowA + off) = l0;
        *(uint32_t*)(sm + X_HI + rowB + off)          = h1;
        *(uint32_t*)(sm + X_HI + XPLANE + rowB + off) = l1;
    }
}

// ---------------- main decoder kernel ----------------
__global__ void __launch_bounds__(NTHR, 2)
decoder_kernel(const float* __restrict__ coords,
               const float* __restrict__ b_in,
               const float* __restrict__ b_skip,
               const float* __restrict__ b_before,
               const float* __restrict__ b_after,
               const float* __restrict__ b_out,
               float* __restrict__ out) {
    extern __shared__ unsigned char sm[];
    const uint32_t sb = smem_u32(sm);
    const int tid  = threadIdx.x;
    const int lane = tid & 31;
    const int warp = tid >> 5;
    const int mt   = warp & 3;      // m-tile 0..3
    const int nh   = warp >> 2;     // n-half 0..1
    const int base = blockIdx.x * NP;

    float* bS = (float*)(sm + SM_BIAS);
    float* cS = (float*)(sm + SM_COORD);

    // prefetch first two weight slots (overlaps with gather)
    cpa_stage(sb + W_A, g_wp + 0 * WPLANE, WPLANE, tid); CPA_COMMIT();   // w_in
    cpa_stage(sb + W_B, g_wp + 1 * WPLANE, WPLANE, tid); CPA_COMMIT();   // w_skip

    // coords + biases
    for (int i = tid; i < NP * 3; i += NTHR) cS[i] = coords[base * 3 + i];
    for (int i = tid; i < 772; i += NTHR) {
        float v;
        if (i < 128)      v = b_in[i];
        else if (i < 256) v = b_skip[i - 128];
        else if (i < 512) v = b_before[i - 256];
        else if (i < 768) v = b_after[i - 512];
        else              v = b_out[i - 768];
        bS[i] = v;
    }
    // zero H pad cols 68..79 (hi+lo): 64 rows x 12 cols, 4 threads/row
    {
        int p = tid >> 2, q = tid & 3;
        #pragma unroll
        for (int j = 0; j < 3; j++) {
            int k = FIN + q * 3 + j;
            int off = (p * HSTR + k) * 2;
            *(uint16_t*)(sm + H_HI + off)          = 0;
            *(uint16_t*)(sm + H_HI + HPLANE + off) = 0;
        }
    }
    __syncthreads();

    // ---- gather + freq encode -> H (fp16 hi/lo, stride 88): 4 threads/point ----
    {
        const int p = tid >> 2;
        const int q = tid & 3;
        const float c0 = cS[p * 3 + 0];
        const float c1 = cS[p * 3 + 1];
        const float c2 = cS[p * 3 + 2];
        const float nrm[3] = {(c0 + 1.0f) * 0.5f, (c1 + 1.0f) * 0.5f, (c2 + 1.0f) * 0.5f};

        for (int a = q; a < 18; a += 4) {
            int d = a / 6;
            int k = a - 6 * d;
            float freq = 3.14159265358979f * (float)(1 << k);
            float s, c;
            sincosf(nrm[d] * freq, &s, &c);
            int k1 = d * 12 + k, k2 = d * 12 + 6 + k;
            int o1 = (p * HSTR + k1) * 2, o2 = (p * HSTR + k2) * 2;
            __half h1 = __float2half_rn(s);
            __half h2 = __float2half_rn(c);
            *(__half*)(sm + H_HI + o1)          = h1;
            *(__half*)(sm + H_HI + HPLANE + o1) = __float2half_rn(s - __half2float(h1));
            *(__half*)(sm + H_HI + o2)          = h2;
            *(__half*)(sm + H_HI + HPLANE + o2) = __float2half_rn(c - __half2float(h2));
        }

        const int b = (base + p) >> 16;
        const float gpx[3] = {c0, c0, c1};
        const float gpy[3] = {c1, c2, c2};
        float acc[8];
        #pragma unroll
        for (int j = 0; j < 8; j++) acc[j] = 0.0f;

        #pragma unroll
        for (int pl = 0; pl < 3; pl++) {
            float ix = (gpx[pl] + 1.0f) * 127.5f;
            float iy = (gpy[pl] + 1.0f) * 127.5f;
            float x0f = floorf(ix), y0f = floorf(iy);
            float fx = ix - x0f, fy = iy - y0f;
            int x0 = min(max((int)x0f, 0), RES - 2);
            int y0 = min(max((int)y0f, 0), RES - 2);
            float w00 = (1.0f - fx) * (1.0f - fy);
            float w10 = fx * (1.0f - fy);
            float w01 = (1.0f - fx) * fy;
            float w11 = fx * fy;
            const float* bp = g_tp + ((size_t)(b * 3 + pl) * (RES * RES) + y0 * RES + x0) * TD + q * 8;
            #pragma unroll
            for (int c = 0; c < 2; c++) {
                float4 v00 = *(const float4*)(bp + c * 4);
                float4 v10 = *(const float4*)(bp + TD + c * 4);
                float4 v01 = *(const float4*)(bp + RES * TD + c * 4);
                float4 v11 = *(const float4*)(bp + RES * TD + TD + c * 4);
                acc[c * 4 + 0] += w00 * v00.x + w10 * v10.x + w01 * v01.x + w11 * v11.x;
                acc[c * 4 + 1] += w00 * v00.y + w10 * v10.y + w01 * v01.y + w11 * v11.y;
                acc[c * 4 + 2] += w00 * v00.z + w10 * v10.z + w01 * v01.z + w11 * v11.z;
                acc[c * 4 + 3] += w00 * v00.w + w10 * v10.w + w01 * v01.w + w11 * v11.w;
            }
        }
        #pragma unroll
        for (int j = 0; j < 8; j++) {
            int k = CD + q * 8 + j;
            int off = (p * HSTR + k) * 2;
            __half h = __float2half_rn(acc[j]);
            *(__half*)(sm + H_HI + off)          = h;
            *(__half*)(sm + H_HI + HPLANE + off) = __float2half_rn(acc[j] - __half2float(h));
        }
    }

    // per-thread fragment addresses
    const int rowM = mt * 16 + (lane & 15);
    const uint32_t aX = sb + X_HI + (uint32_t)((rowM * STRIDE + (lane >> 4) * 8) * 2);
    const uint32_t aH = sb + H_HI + (uint32_t)((rowM * HSTR + (lane >> 4) * 8) * 2);
    const uint32_t bOff4 = (uint32_t)(nh * 8 * (8 * ROWB)) +
        (uint32_t)((((lane & 7) + (lane >> 4) * 8) * STRIDE + ((lane >> 3) & 1) * 8) * 2);
    const uint32_t bA4 = sb + W_A + bOff4, bB4 = sb + W_B + bOff4;
    const uint32_t bA2 = sb + W_A +
        (uint32_t)(((lane & 7) * STRIDE + ((lane >> 3) & 1) * 8) * 2);

    const int g    = lane >> 2;
    const int tig  = lane & 3;
    const int pA   = mt * 16 + g;
    const int colb = nh * 64;

    float D[8][4];
    float S[8][4];

    // L1: D = Win h  (W_A)
    CPA_WAIT1();                       // w_in arrived
    __syncthreads();
    mma_layer8<5, HPLANE>(aH, bA4, D);
    __syncthreads();                   // all done reading W_A
    cpa_stage(sb + W_A, g_wp + 2 * WPLANE, WPLANE, tid); CPA_COMMIT();   // w_b0 -> W_A
    CPA_WAIT1();                       // w_skip arrived
    __syncthreads();

    // skip: S = Wskip h  (W_B; H still live)
    mma_layer8<5, HPLANE>(aH, bB4, S);
    __syncthreads();                   // all done reading W_B + H
    cpa_stage(sb + W_B, g_wp + 3 * WPLANE, WPLANE, tid); CPA_COMMIT();   // w_b1 -> W_B
    epi<false>(sm, D, S, bS + 0 + colb, nullptr, pA, tig, colb);         // x1 -> X (H dead)
    CPA_WAIT1();                       // w_b0 arrived
    __syncthreads();

    // L2: D = W0 x1  (W_A)
    mma_layer8<8, XPLANE>(aX, bA4, D);
    __syncthreads();
    cpa_stage(sb + W_A, g_wp + 4 * WPLANE, WPLANE, tid); CPA_COMMIT();   // w_a0 -> W_A
    epi<false>(sm, D, S, bS + 256 + colb, nullptr, pA, tig, colb);       // x2 -> X
    CPA_WAIT1();                       // w_b1 arrived
    __syncthreads();

    // L3: D = W1 x2  (W_B); combine with skip S
    mma_layer8<8, XPLANE>(aX, bB4, D);
    __syncthreads();
    cpa_stage(sb + W_B, g_wp + 5 * WPLANE, WPLANE, tid); CPA_COMMIT();   // w_a1 -> W_B
    epi<true>(sm, D, S, bS + 384 + colb, bS + 128 + colb, pA, tig, colb); // x4 -> X
    CPA_WAIT1();                       // w_a0 arrived
    __syncthreads();

    // L4: D = W2 x4  (W_A)
    mma_layer8<8, XPLANE>(aX, bA4, D);
    __syncthreads();
    cpa_stage(sb + W_A, g_wp + 6 * WPLANE, 8 * ROWB, tid); CPA_COMMIT(); // w_out -> W_A
    epi<false>(sm, D, S, bS + 512 + colb, nullptr, pA, tig, colb);       // x5 -> X
    CPA_WAIT1();                       // w_a1 arrived
    __syncthreads();

    // L5: D = W3 x5  (W_B)
    mma_layer8<8, XPLANE>(aX, bB4, D);
    __syncthreads();
    epi<false>(sm, D, S, bS + 640 + colb, nullptr, pA, tig, colb);       // x6 -> X
    CPA_WAIT0();                       // w_out arrived
    __syncthreads();

    // L6: out = Wout x6 (n-half 0 warps; cols 0..3 valid)
    if (nh == 0) {
        float Do[4];
        mma_layer1<8>(aX, bA2, Do);
        const int pB  = pA + 8;
        const int gpA = base + pA, gpB = base + pB;
        if (tig == 0) {
            float v0 = Do[0] + bS[768], v1 = Do[1] + bS[769];
            float v2 = Do[2] + bS[768], v3 = Do[3] + bS[769];
            out[gpA * 3 + 0] = 1.0f / (1.0f + expf(-v0));
            out[gpA * 3 + 1] = 1.0f / (1.0f + expf(-v1));
            out[gpB * 3 + 0] = 1.0f / (1.0f + expf(-v2));
            out[gpB * 3 + 1] = 1.0f / (1.0f + expf(-v3));
        } else if (tig == 1) {
            float v0 = Do[0] + bS[770], v1 = Do[1] + bS[771];
            float v2 = Do[2] + bS[770], v3 = Do[3] + bS[771];
            out[gpA * 3 + 2] = 1.0f / (1.0f + expf(-v0));
            out[gpB * 3 + 2] = 1.0f / (1.0f + expf(-v2));
            float a0 = cS[pA * 3 + 0], a1 = cS[pA * 3 + 1], a2 = cS[pA * 3 + 2];
            bool selA = (a0 > -1.0f) && (a0 < 1.0f) && (a1 > -1.0f) && (a1 < 1.0f) &&
                        (a2 > -1.0f) && (a2 < 1.0f);
            float b0 = cS[pB * 3 + 0], b1 = cS[pB * 3 + 1], b2 = cS[pB * 3 + 2];
            bool selB = (b0 > -1.0f) && (b0 < 1.0f) && (b1 > -1.0f) && (b1 < 1.0f) &&
                        (b2 > -1.0f) && (b2 < 1.0f);
            out[3 * NPTS + gpA] = selA ? expf(v1 - 1.0f) : 0.0f;
            out[3 * NPTS + gpB] = selB ? expf(v3 - 1.0f) : 0.0f;
        }
    }
}

// ---------------- launch ----------------
extern "C" void kernel_launch(void* const* d_in, const int* in_sizes, int n_in,
                              void* d_out, int out_size) {
    const float* triplane = (const float*)d_in[0];
    const float* coords   = (const float*)d_in[1];
    const float* w_in     = (const float*)d_in[2];
    const float* b_in     = (const float*)d_in[3];
    const float* w_skip   = (const float*)d_in[4];
    const float* b_skip   = (const float*)d_in[5];
    const float* w_before = (const float*)d_in[6];
    const float* b_before = (const float*)d_in[7];
    const float* w_after  = (const float*)d_in[8];
    const float* b_after  = (const float*)d_in[9];
    const float* w_out    = (const float*)d_in[10];
    const float* b_out    = (const float*)d_in[11];
    float* out = (float*)d_out;

    static bool attr_set = false;
    if (!attr_set) {
        cudaFuncSetAttribute(decoder_kernel,
                             cudaFuncAttributeMaxDynamicSharedMemorySize, SMEM_BYTES);
        attr_set = true;
    }

    const int wp_blks = (WP_TOT + 255) / 256;
    prep_all_kernel<<<TP_BLKS + wp_blks, 256>>>(
        triplane, w_in, w_skip, w_before, w_after, w_out);
    decoder_kernel<<<NPTS / NP, NTHR, SMEM_BYTES>>>(
        coords, b_in, b_skip, b_before, b_after, b_out, out);
}

// round 8
// speedup vs baseline: 5.4087x; 1.3077x over previous
#include <cuda_runtime.h>
#include <cuda_fp16.h>
#include <math.h>
#include <stdint.h>

// ---------------- problem constants ----------------
#define BB     4
#define PP     65536
#define NPTS   (BB * PP)
#define TD     32
#define HID    128
#define CD     36
#define FIN    68
#define RES    256

#define NP     64               // points per CTA
#define NTHR   256              // 8 warps: warp&3 = m-tile, warp>>2 = n-half
#define STRIDE 136              // padded row stride (elems) for X and W
#define ROWB   (STRIDE * 2)     // 272 bytes per row
#define WPLANE (128 * ROWB)     // 34816: single fp16 weight plane (128 neurons)
#define XPLANE (NP * ROWB)      // 17408: single fp16 activation plane (64 points)
#define HSTR   88               // H row stride (elems), K range 0..79

// smem layout (bytes). H aliases X (H dies before first X write).
#define X_HI      0             // X plane (17408)
#define H_HI      0             // H plane (11264, aliased under X)
#define W_A       17408         // weight buffer A (34816)
#define W_B       52224         // weight buffer B (34816)
#define SM_BIAS   87040         // 772 floats
#define SM_COORD  90128         // 192 floats
#define SMEM_BYTES 90896

// ---------------- device scratch ----------------
__device__ __align__(16) float g_tp[12 * RES * RES * TD];
// slots 0=w_in 1=w_skip 2=w_b0 3=w_b1 4=w_a0 5=w_a1 (WPLANE each, fp16), 6=w_out (8*ROWB)
__device__ __align__(16) unsigned char g_wp[6 * WPLANE + 8 * ROWB];

// ---------------- helpers ----------------
__device__ __forceinline__ uint32_t smem_u32(const void* p) {
    uint32_t a;
    asm("{ .reg .u64 t; cvta.to.shared.u64 t, %1; cvt.u32.u64 %0, t; }" : "=r"(a) : "l"(p));
    return a;
}
__device__ __forceinline__ void ldsm4(uint32_t a, uint32_t r[4]) {
    asm volatile("ldmatrix.sync.aligned.m8n8.x4.shared.b16 {%0,%1,%2,%3}, [%4];"
                 : "=r"(r[0]), "=r"(r[1]), "=r"(r[2]), "=r"(r[3]) : "r"(a));
}
__device__ __forceinline__ void ldsm2(uint32_t a, uint32_t r[2]) {
    asm volatile("ldmatrix.sync.aligned.m8n8.x2.shared.b16 {%0,%1}, [%2];"
                 : "=r"(r[0]), "=r"(r[1]) : "r"(a));
}
__device__ __forceinline__ void mma16816(float d[4], const uint32_t a[4], const uint32_t b[2]) {
    asm volatile("mma.sync.aligned.m16n8k16.row.col.f32.f16.f16.f32 "
                 "{%0,%1,%2,%3}, {%4,%5,%6,%7}, {%8,%9}, {%0,%1,%2,%3};"
                 : "+f"(d[0]), "+f"(d[1]), "+f"(d[2]), "+f"(d[3])
                 : "r"(a[0]), "r"(a[1]), "r"(a[2]), "r"(a[3]), "r"(b[0]), "r"(b[1]));
}

// cp.async
__device__ __forceinline__ void cpa_stage(uint32_t dst, const unsigned char* src, int bytes, int tid) {
    for (int i = tid * 16; i < bytes; i += NTHR * 16)
        asm volatile("cp.async.cg.shared.global [%0], [%1], 16;" :: "r"(dst + i), "l"(src + i) : "memory");
}
#define CPA_COMMIT()  asm volatile("cp.async.commit_group;" ::: "memory")
#define CPA_WAIT0()   asm volatile("cp.async.wait_group 0;" ::: "memory")
#define CPA_WAIT1()   asm volatile("cp.async.wait_group 1;" ::: "memory")

// ---------------- merged prep kernel ----------------
#define TP_BLKS (12 * 512)
#define WP_TOT  (6 * 128 * STRIDE + 8 * STRIDE)
__global__ void prep_all_kernel(const float* __restrict__ tri,
                                const float* __restrict__ w_in,
                                const float* __restrict__ w_skip,
                                const float* __restrict__ w_before,
                                const float* __restrict__ w_after,
                                const float* __restrict__ w_out) {
    __shared__ float t[32 * 129 + 4];
    const int blk = blockIdx.x;
    const int tid = threadIdx.x;
    if (blk < TP_BLKS) {
        const int n   = blk >> 9;
        const int hw0 = (blk & 511) * 128;
        const int c   = tid >> 3;
        const int h8  = tid & 7;
        const float* src = tri + (size_t)(n * 32 + c) * 65536 + hw0;
        #pragma unroll
        for (int i = 0; i < 4; i++) {
            int hw = i * 32 + h8 * 4;
            float4 v = *(const float4*)(src + hw);
            float* tr = t + c * 129 + hw;
            tr[0] = v.x; tr[1] = v.y; tr[2] = v.z; tr[3] = v.w;
        }
        __syncthreads();
        #pragma unroll
        for (int i = 0; i < 4; i++) {
            int e  = tid + 256 * i;
            int hw = e >> 3, c4 = e & 7;
            float4 v = make_float4(t[(4 * c4 + 0) * 129 + hw], t[(4 * c4 + 1) * 129 + hw],
                                   t[(4 * c4 + 2) * 129 + hw], t[(4 * c4 + 3) * 129 + hw]);
            *(float4*)(g_tp + ((size_t)n * 65536 + hw0 + hw) * 32 + c4 * 4) = v;
        }
        return;
    }
    int idx = (blk - TP_BLKS) * 256 + tid;
    if (idx >= WP_TOT) return;
    const int HN = 6 * 128 * STRIDE;
    int slot, o, k;
    size_t sbase;
    if (idx < HN) {
        slot = idx / (128 * STRIDE);
        int e = idx % (128 * STRIDE);
        o = e / STRIDE; k = e % STRIDE;
        sbase = (size_t)slot * WPLANE;
    } else {
        slot = 6;
        int e = idx - HN;
        o = e / STRIDE; k = e % STRIDE;
        sbase = (size_t)6 * WPLANE;
    }
    float v = 0.0f;
    switch (slot) {
        case 0: if (k < FIN) v = w_in[o * FIN + k]; break;
        case 1: if (k < FIN) v = w_skip[o * FIN + k]; break;
        case 2: if (k < HID) v = w_before[o * HID + k]; break;
        case 3: if (k < HID) v = w_before[HID * HID + o * HID + k]; break;
        case 4: if (k < HID) v = w_after[o * HID + k]; break;
        case 5: if (k < HID) v = w_after[HID * HID + o * HID + k]; break;
        case 6: if (o < 4 && k < HID) v = w_out[o * HID + k]; break;
    }
    *(__half*)(g_wp + sbase + (size_t)(o * STRIDE + k) * 2) = __float2half_rn(v);
}

// ---------------- MMA layers ----------------
// 8 n-tiles (this warp's 64-neuron half); pure fp16: D = A * B.
template <int KS>
__device__ __forceinline__ void mma_layer8(uint32_t aA, uint32_t bB4, float D[8][4]) {
    #pragma unroll
    for (int nt = 0; nt < 8; nt++) { D[nt][0] = 0.f; D[nt][1] = 0.f; D[nt][2] = 0.f; D[nt][3] = 0.f; }
    #pragma unroll
    for (int k = 0; k < KS; k++) {
        uint32_t Ah[4];
        ldsm4(aA + k * 32, Ah);
        #pragma unroll
        for (int nt = 0; nt < 8; nt += 2) {
            uint32_t Bh[4];
            ldsm4(bB4 + nt * (8 * ROWB) + k * 32, Bh);
            mma16816(D[nt],     Ah, Bh);
            mma16816(D[nt + 1], Ah, Bh + 2);
        }
    }
}

// single n-tile (output layer)
template <int KS>
__device__ __forceinline__ void mma_layer1(uint32_t aA, uint32_t bB2, float d[4]) {
    d[0] = d[1] = d[2] = d[3] = 0.f;
    #pragma unroll
    for (int k = 0; k < KS; k++) {
        uint32_t Ah[4], Bh[2];
        ldsm4(aA + k * 32, Ah);
        ldsm2(bB2 + k * 32, Bh);
        mma16816(d, Ah, Bh);
    }
}

// epilogue: bias + relu (+ skip), fp16 pack, store into X (warp-private rows/cols).
template <bool SK>
__device__ __forceinline__ void epi(unsigned char* sm, float D[8][4], float S[8][4],
                                    const float* bd, const float* bs,
                                    int pA, int tig, int colb) {
    const int rowA = pA * ROWB;
    const int rowB = rowA + 8 * ROWB;
    #pragma unroll
    for (int nt = 0; nt < 8; nt++) {
        int c0 = nt * 8 + 2 * tig;
        float b0 = bd[c0], b1 = bd[c0 + 1];
        float x0 = fmaxf(D[nt][0] + b0, 0.f), x1 = fmaxf(D[nt][1] + b1, 0.f);
        float x2 = fmaxf(D[nt][2] + b0, 0.f), x3 = fmaxf(D[nt][3] + b1, 0.f);
        if (SK) {
            float s0 = bs[c0], s1 = bs[c0 + 1];
            x0 += fmaxf(S[nt][0] + s0, 0.f); x1 += fmaxf(S[nt][1] + s1, 0.f);
            x2 += fmaxf(S[nt][2] + s0, 0.f); x3 += fmaxf(S[nt][3] + s1, 0.f);
        }
        __half2 h0 = __floats2half2_rn(x0, x1);
        __half2 h1 = __floats2half2_rn(x2, x3);
        int off = (colb + c0) * 2;
        *(uint32_t*)(sm + X_HI + rowA + off) = *(uint32_t*)&h0;
        *(uint32_t*)(sm + X_HI + rowB + off) = *(uint32_t*)&h1;
    }
}

// ---------------- main decoder kernel ----------------
__global__ void __launch_bounds__(NTHR, 2)
decoder_kernel(const float* __restrict__ coords,
               const float* __restrict__ b_in,
               const float* __restrict__ b_skip,
               const float* __restrict__ b_before,
               const float* __restrict__ b_after,
               const float* __restrict__ b_out,
               float* __restrict__ out) {
    extern __shared__ unsigned char sm[];
    const uint32_t sb = smem_u32(sm);
    const int tid  = threadIdx.x;
    const int lane = tid & 31;
    const int warp = tid >> 5;
    const int mt   = warp & 3;      // m-tile 0..3
    const int nh   = warp >> 2;     // n-half 0..1
    const int base = blockIdx.x * NP;

    float* bS = (float*)(sm + SM_BIAS);
    float* cS = (float*)(sm + SM_COORD);

    // prefetch first two weight slots (overlaps with gather)
    cpa_stage(sb + W_A, g_wp + 0 * WPLANE, WPLANE, tid); CPA_COMMIT();   // w_in
    cpa_stage(sb + W_B, g_wp + 1 * WPLANE, WPLANE, tid); CPA_COMMIT();   // w_skip

    // coords + biases
    for (int i = tid; i < NP * 3; i += NTHR) cS[i] = coords[base * 3 + i];
    for (int i = tid; i < 772; i += NTHR) {
        float v;
        if (i < 128)      v = b_in[i];
        else if (i < 256) v = b_skip[i - 128];
        else if (i < 512) v = b_before[i - 256];
        else if (i < 768) v = b_after[i - 512];
        else              v = b_out[i - 768];
        bS[i] = v;
    }
    // zero H pad cols 68..79: 64 rows x 12 cols, 4 threads/row
    {
        int p = tid >> 2, q = tid & 3;
        #pragma unroll
        for (int j = 0; j < 3; j++) {
            int k = FIN + q * 3 + j;
            *(uint16_t*)(sm + H_HI + (p * HSTR + k) * 2) = 0;
        }
    }
    __syncthreads();

    // ---- gather + freq encode -> H (fp16, stride 88): 4 threads/point ----
    {
        const int p = tid >> 2;
        const int q = tid & 3;
        const float c0 = cS[p * 3 + 0];
        const float c1 = cS[p * 3 + 1];
        const float c2 = cS[p * 3 + 2];
        const float nrm[3] = {(c0 + 1.0f) * 0.5f, (c1 + 1.0f) * 0.5f, (c2 + 1.0f) * 0.5f};

        for (int a = q; a < 18; a += 4) {
            int d = a / 6;
            int k = a - 6 * d;
            float freq = 3.14159265358979f * (float)(1 << k);
            float s, c;
            sincosf(nrm[d] * freq, &s, &c);
            int k1 = d * 12 + k, k2 = d * 12 + 6 + k;
            *(__half*)(sm + H_HI + (p * HSTR + k1) * 2) = __float2half_rn(s);
            *(__half*)(sm + H_HI + (p * HSTR + k2) * 2) = __float2half_rn(c);
        }

        const int b = (base + p) >> 16;
        const float gpx[3] = {c0, c0, c1};
        const float gpy[3] = {c1, c2, c2};
        float acc[8];
        #pragma unroll
        for (int j = 0; j < 8; j++) acc[j] = 0.0f;

        #pragma unroll
        for (int pl = 0; pl < 3; pl++) {
            float ix = (gpx[pl] + 1.0f) * 127.5f;
            float iy = (gpy[pl] + 1.0f) * 127.5f;
            float x0f = floorf(ix), y0f = floorf(iy);
            float fx = ix - x0f, fy = iy - y0f;
            int x0 = min(max((int)x0f, 0), RES - 2);
            int y0 = min(max((int)y0f, 0), RES - 2);
            float w00 = (1.0f - fx) * (1.0f - fy);
            float w10 = fx * (1.0f - fy);
            float w01 = (1.0f - fx) * fy;
            float w11 = fx * fy;
            const float* bp = g_tp + ((size_t)(b * 3 + pl) * (RES * RES) + y0 * RES + x0) * TD + q * 8;
            #pragma unroll
            for (int c = 0; c < 2; c++) {
                float4 v00 = *(const float4*)(bp + c * 4);
                float4 v10 = *(const float4*)(bp + TD + c * 4);
                float4 v01 = *(const float4*)(bp + RES * TD + c * 4);
                float4 v11 = *(const float4*)(bp + RES * TD + TD + c * 4);
                acc[c * 4 + 0] += w00 * v00.x + w10 * v10.x + w01 * v01.x + w11 * v11.x;
                acc[c * 4 + 1] += w00 * v00.y + w10 * v10.y + w01 * v01.y + w11 * v11.y;
                acc[c * 4 + 2] += w00 * v00.z + w10 * v10.z + w01 * v01.z + w11 * v11.z;
                acc[c * 4 + 3] += w00 * v00.w + w10 * v10.w + w01 * v01.w + w11 * v11.w;
            }
        }
        #pragma unroll
        for (int j = 0; j < 8; j++) {
            int k = CD + q * 8 + j;
            *(__half*)(sm + H_HI + (p * HSTR + k) * 2) = __float2half_rn(acc[j]);
        }
    }

    // per-thread fragment addresses
    const int rowM = mt * 16 + (lane & 15);
    const uint32_t aX = sb + X_HI + (uint32_t)((rowM * STRIDE + (lane >> 4) * 8) * 2);
    const uint32_t aH = sb + H_HI + (uint32_t)((rowM * HSTR + (lane >> 4) * 8) * 2);
    const uint32_t bOff4 = (uint32_t)(nh * 8 * (8 * ROWB)) +
        (uint32_t)((((lane & 7) + (lane >> 4) * 8) * STRIDE + ((lane >> 3) & 1) * 8) * 2);
    const uint32_t bA4 = sb + W_A + bOff4, bB4 = sb + W_B + bOff4;
    const uint32_t bA2 = sb + W_A +
        (uint32_t)(((lane & 7) * STRIDE + ((lane >> 3) & 1) * 8) * 2);

    const int g    = lane >> 2;
    const int tig  = lane & 3;
    const int pA   = mt * 16 + g;
    const int colb = nh * 64;

    float D[8][4];
    float S[8][4];

    // L1: D = Win h  (W_A)
    CPA_WAIT1();                       // w_in arrived
    __syncthreads();
    mma_layer8<5>(aH, bA4, D);
    __syncthreads();                   // all done reading W_A
    cpa_stage(sb + W_A, g_wp + 2 * WPLANE, WPLANE, tid); CPA_COMMIT();   // w_b0 -> W_A
    CPA_WAIT1();                       // w_skip arrived
    __syncthreads();

    // skip: S = Wskip h  (W_B; H still live)
    mma_layer8<5>(aH, bB4, S);
    __syncthreads();                   // all done reading W_B + H
    cpa_stage(sb + W_B, g_wp + 3 * WPLANE, WPLANE, tid); CPA_COMMIT();   // w_b1 -> W_B
    epi<false>(sm, D, S, bS + 0 + colb, nullptr, pA, tig, colb);         // x1 -> X (H dead)
    CPA_WAIT1();                       // w_b0 arrived
    __syncthreads();

    // L2: D = W0 x1  (W_A)
    mma_layer8<8>(aX, bA4, D);
    __syncthreads();
    cpa_stage(sb + W_A, g_wp + 4 * WPLANE, WPLANE, tid); CPA_COMMIT();   // w_a0 -> W_A
    epi<false>(sm, D, S, bS + 256 + colb, nullptr, pA, tig, colb);       // x2 -> X
    CPA_WAIT1();                       // w_b1 arrived
    __syncthreads();

    // L3: D = W1 x2  (W_B); combine with skip S
    mma_layer8<8>(aX, bB4, D);
    __syncthreads();
    cpa_stage(sb + W_B, g_wp + 5 * WPLANE, WPLANE, tid); CPA_COMMIT();   // w_a1 -> W_B
    epi<true>(sm, D, S, bS + 384 + colb, bS + 128 + colb, pA, tig, colb); // x4 -> X
    CPA_WAIT1();                       // w_a0 arrived
    __syncthreads();

    // L4: D = W2 x4  (W_A)
    mma_layer8<8>(aX, bA4, D);
    __syncthreads();
    cpa_stage(sb + W_A, g_wp + 6 * WPLANE, 8 * ROWB, tid); CPA_COMMIT(); // w_out -> W_A
    epi<false>(sm, D, S, bS + 512 + colb, nullptr, pA, tig, colb);       // x5 -> X
    CPA_WAIT1();                       // w_a1 arrived
    __syncthreads();

    // L5: D = W3 x5  (W_B)
    mma_layer8<8>(aX, bB4, D);
    __syncthreads();
    epi<false>(sm, D, S, bS + 640 + colb, nullptr, pA, tig, colb);       // x6 -> X
    CPA_WAIT0();                       // w_out arrived
    __syncthreads();

    // L6: out = Wout x6 (n-half 0 warps; cols 0..3 valid)
    if (nh == 0) {
        float Do[4];
        mma_layer1<8>(aX, bA2, Do);
        const int pB  = pA + 8;
        const int gpA = base + pA, gpB = base + pB;
        if (tig == 0) {
            float v0 = Do[0] + bS[768], v1 = Do[1] + bS[769];
            float v2 = Do[2] + bS[768], v3 = Do[3] + bS[769];
            out[gpA * 3 + 0] = 1.0f / (1.0f + expf(-v0));
            out[gpA * 3 + 1] = 1.0f / (1.0f + expf(-v1));
            out[gpB * 3 + 0] = 1.0f / (1.0f + expf(-v2));
            out[gpB * 3 + 1] = 1.0f / (1.0f + expf(-v3));
        } else if (tig == 1) {
            float v0 = Do[0] + bS[770], v1 = Do[1] + bS[771];
            float v2 = Do[2] + bS[770], v3 = Do[3] + bS[771];
            out[gpA * 3 + 2] = 1.0f / (1.0f + expf(-v0));
            out[gpB * 3 + 2] = 1.0f / (1.0f + expf(-v2));
            float a0 = cS[pA * 3 + 0], a1 = cS[pA * 3 + 1], a2 = cS[pA * 3 + 2];
            bool selA = (a0 > -1.0f) && (a0 < 1.0f) && (a1 > -1.0f) && (a1 < 1.0f) &&
                        (a2 > -1.0f) && (a2 < 1.0f);
            float b0 = cS[pB * 3 + 0], b1 = cS[pB * 3 + 1], b2 = cS[pB * 3 + 2];
            bool selB = (b0 > -1.0f) && (b0 < 1.0f) && (b1 > -1.0f) && (b1 < 1.0f) &&
                        (b2 > -1.0f) && (b2 < 1.0f);
            out[3 * NPTS + gpA] = selA ? expf(v1 - 1.0f) : 0.0f;
            out[3 * NPTS + gpB] = selB ? expf(v3 - 1.0f) : 0.0f;
        }
    }
}

// ---------------- launch ----------------
extern "C" void kernel_launch(void* const* d_in, const int* in_sizes, int n_in,
                              void* d_out, int out_size) {
    const float* triplane = (const float*)d_in[0];
    const float* coords   = (const float*)d_in[1];
    const float* w_in     = (const float*)d_in[2];
    const float* b_in     = (const float*)d_in[3];
    const float* w_skip   = (const float*)d_in[4];
    const float* b_skip   = (const float*)d_in[5];
    const float* w_before = (const float*)d_in[6];
    const float* b_before = (const float*)d_in[7];
    const float* w_after  = (const float*)d_in[8];
    const float* b_after  = (const float*)d_in[9];
    const float* w_out    = (const float*)d_in[10];
    const float* b_out    = (const float*)d_in[11];
    float* out = (float*)d_out;

    static bool attr_set = false;
    if (!attr_set) {
        cudaFuncSetAttribute(decoder_kernel,
                             cudaFuncAttributeMaxDynamicSharedMemorySize, SMEM_BYTES);
        attr_set = true;
    }

    const int wp_blks = (WP_TOT + 255) / 256;
    prep_all_kernel<<<TP_BLKS + wp_blks, 256>>>(
        triplane, w_in, w_skip, w_before, w_after, w_out);
    decoder_kernel<<<NPTS / NP, NTHR, SMEM_BYTES>>>(
        coords, b_in, b_skip, b_before, b_after, b_out, out);
}

// round 9
// speedup vs baseline: 5.8355x; 1.0789x over previous
#include <cuda_runtime.h>
#include <cuda_fp16.h>
#include <math.h>
#include <stdint.h>

// ---------------- problem constants ----------------
#define BB     4
#define PP     65536
#define NPTS   (BB * PP)
#define TD     32
#define HID    128
#define CD     36
#define FIN    68
#define RES    256

#define NP     64               // points per CTA
#define NTHR   256              // 8 warps: warp&1 = m-half (32 rows), warp>>1 = n-group (32 cols)
#define STRIDE 136              // padded row stride (elems) for X and W
#define ROWB   (STRIDE * 2)     // 272 bytes per row
#define WPLANE (128 * ROWB)     // 34816: single fp16 weight plane (128 neurons)
#define XPLANE (NP * ROWB)      // 17408: single fp16 activation plane (64 points)
#define HSTR   88               // H row stride (elems), K range 0..79
#define HROWB  (HSTR * 2)       // 176

// smem layout (bytes). H aliases X (H dies before first X write).
#define X_HI      0             // X plane (17408)
#define H_HI      0             // H plane (11264, aliased under X)
#define W_A       17408         // weight buffer A (34816)
#define W_B       52224         // weight buffer B (34816)
#define SM_BIAS   87040         // 772 floats
#define SM_COORD  90128         // 192 floats
#define SMEM_BYTES 90896

// ---------------- device scratch ----------------
__device__ __align__(16) float g_tp[12 * RES * RES * TD];
// slots 0=w_in 1=w_skip 2=w_b0 3=w_b1 4=w_a0 5=w_a1 (WPLANE each, fp16), 6=w_out (8*ROWB)
__device__ __align__(16) unsigned char g_wp[6 * WPLANE + 8 * ROWB];

// ---------------- helpers ----------------
__device__ __forceinline__ uint32_t smem_u32(const void* p) {
    uint32_t a;
    asm("{ .reg .u64 t; cvta.to.shared.u64 t, %1; cvt.u32.u64 %0, t; }" : "=r"(a) : "l"(p));
    return a;
}
__device__ __forceinline__ void ldsm4(uint32_t a, uint32_t r[4]) {
    asm volatile("ldmatrix.sync.aligned.m8n8.x4.shared.b16 {%0,%1,%2,%3}, [%4];"
                 : "=r"(r[0]), "=r"(r[1]), "=r"(r[2]), "=r"(r[3]) : "r"(a));
}
__device__ __forceinline__ void ldsm2(uint32_t a, uint32_t r[2]) {
    asm volatile("ldmatrix.sync.aligned.m8n8.x2.shared.b16 {%0,%1}, [%2];"
                 : "=r"(r[0]), "=r"(r[1]) : "r"(a));
}
__device__ __forceinline__ void mma16816(float d[4], const uint32_t a[4], const uint32_t b[2]) {
    asm volatile("mma.sync.aligned.m16n8k16.row.col.f32.f16.f16.f32 "
                 "{%0,%1,%2,%3}, {%4,%5,%6,%7}, {%8,%9}, {%0,%1,%2,%3};"
                 : "+f"(d[0]), "+f"(d[1]), "+f"(d[2]), "+f"(d[3])
                 : "r"(a[0]), "r"(a[1]), "r"(a[2]), "r"(a[3]), "r"(b[0]), "r"(b[1]));
}

// cp.async
__device__ __forceinline__ void cpa_stage(uint32_t dst, const unsigned char* src, int bytes, int tid) {
    for (int i = tid * 16; i < bytes; i += NTHR * 16)
        asm volatile("cp.async.cg.shared.global [%0], [%1], 16;" :: "r"(dst + i), "l"(src + i) : "memory");
}
#define CPA_COMMIT()  asm volatile("cp.async.commit_group;" ::: "memory")
#define CPA_WAIT0()   asm volatile("cp.async.wait_group 0;" ::: "memory")
#define CPA_WAIT1()   asm volatile("cp.async.wait_group 1;" ::: "memory")

// ---------------- merged prep kernel ----------------
#define TP_BLKS (12 * 512)
#define WP_TOT  (6 * 128 * STRIDE + 8 * STRIDE)
__global__ void prep_all_kernel(const float* __restrict__ tri,
                                const float* __restrict__ w_in,
                                const float* __restrict__ w_skip,
                                const float* __restrict__ w_before,
                                const float* __restrict__ w_after,
                                const float* __restrict__ w_out) {
    __shared__ float t[32 * 129 + 4];
    const int blk = blockIdx.x;
    const int tid = threadIdx.x;
    if (blk < TP_BLKS) {
        const int n   = blk >> 9;
        const int hw0 = (blk & 511) * 128;
        const int c   = tid >> 3;
        const int h8  = tid & 7;
        const float* src = tri + (size_t)(n * 32 + c) * 65536 + hw0;
        #pragma unroll
        for (int i = 0; i < 4; i++) {
            int hw = i * 32 + h8 * 4;
            float4 v = *(const float4*)(src + hw);
            float* tr = t + c * 129 + hw;
            tr[0] = v.x; tr[1] = v.y; tr[2] = v.z; tr[3] = v.w;
        }
        __syncthreads();
        #pragma unroll
        for (int i = 0; i < 4; i++) {
            int e  = tid + 256 * i;
            int hw = e >> 3, c4 = e & 7;
            float4 v = make_float4(t[(4 * c4 + 0) * 129 + hw], t[(4 * c4 + 1) * 129 + hw],
                                   t[(4 * c4 + 2) * 129 + hw], t[(4 * c4 + 3) * 129 + hw]);
            *(float4*)(g_tp + ((size_t)n * 65536 + hw0 + hw) * 32 + c4 * 4) = v;
        }
        return;
    }
    int idx = (blk - TP_BLKS) * 256 + tid;
    if (idx >= WP_TOT) return;
    const int HN = 6 * 128 * STRIDE;
    int slot, o, k;
    size_t sbase;
    if (idx < HN) {
        slot = idx / (128 * STRIDE);
        int e = idx % (128 * STRIDE);
        o = e / STRIDE; k = e % STRIDE;
        sbase = (size_t)slot * WPLANE;
    } else {
        slot = 6;
        int e = idx - HN;
        o = e / STRIDE; k = e % STRIDE;
        sbase = (size_t)6 * WPLANE;
    }
    float v = 0.0f;
    switch (slot) {
        case 0: if (k < FIN) v = w_in[o * FIN + k]; break;
        case 1: if (k < FIN) v = w_skip[o * FIN + k]; break;
        case 2: if (k < HID) v = w_before[o * HID + k]; break;
        case 3: if (k < HID) v = w_before[HID * HID + o * HID + k]; break;
        case 4: if (k < HID) v = w_after[o * HID + k]; break;
        case 5: if (k < HID) v = w_after[HID * HID + o * HID + k]; break;
        case 6: if (o < 4 && k < HID) v = w_out[o * HID + k]; break;
    }
    *(__half*)(g_wp + sbase + (size_t)(o * STRIDE + k) * 2) = __float2half_rn(v);
}

// ---------------- MMA layer ----------------
// Warp computes 32 M-rows (two 16-row subtiles, A16 bytes apart) x 4 n-tiles (32 neurons).
// D index = mi*4 + ntl.  Pure fp16: D = A * B.
template <int KS, int A16>
__device__ __forceinline__ void mma_layer(uint32_t aA, uint32_t bB4, float D[8][4]) {
    #pragma unroll
    for (int i = 0; i < 8; i++) { D[i][0] = 0.f; D[i][1] = 0.f; D[i][2] = 0.f; D[i][3] = 0.f; }
    #pragma unroll
    for (int k = 0; k < KS; k++) {
        uint32_t A0[4], A1[4];
        ldsm4(aA + k * 32, A0);
        ldsm4(aA + A16 + k * 32, A1);
        #pragma unroll
        for (int p = 0; p < 2; p++) {
            uint32_t Bh[4];
            ldsm4(bB4 + p * (16 * ROWB) + k * 32, Bh);
            mma16816(D[p * 2],         A0, Bh);
            mma16816(D[p * 2 + 1],     A0, Bh + 2);
            mma16816(D[4 + p * 2],     A1, Bh);
            mma16816(D[4 + p * 2 + 1], A1, Bh + 2);
        }
    }
}

// single n-tile (output layer), 16 rows
template <int KS>
__device__ __forceinline__ void mma_layer1(uint32_t aA, uint32_t bB2, float d[4]) {
    d[0] = d[1] = d[2] = d[3] = 0.f;
    #pragma unroll
    for (int k = 0; k < KS; k++) {
        uint32_t Ah[4], Bh[2];
        ldsm4(aA + k * 32, Ah);
        ldsm2(bB2 + k * 32, Bh);
        mma16816(d, Ah, Bh);
    }
}

// epilogue: bias + relu (+ skip), fp16 pack, store into X.
// Warp owns rows mt*32 + mi*16 + {g, g+8}, cols colb + ntl*8 + 2*tig + {0,1}.
template <bool SK>
__device__ __forceinline__ void epi(unsigned char* sm, float D[8][4], float S[8][4],
                                    const float* bd, const float* bs,
                                    int pBase, int tig, int colb) {
    #pragma unroll
    for (int mi = 0; mi < 2; mi++) {
        const int rowA = (pBase + mi * 16) * ROWB;
        const int rowB = rowA + 8 * ROWB;
        #pragma unroll
        for (int ntl = 0; ntl < 4; ntl++) {
            int idx = mi * 4 + ntl;
            int c0 = colb + ntl * 8 + 2 * tig;
            float b0 = bd[c0], b1 = bd[c0 + 1];
            float x0 = fmaxf(D[idx][0] + b0, 0.f), x1 = fmaxf(D[idx][1] + b1, 0.f);
            float x2 = fmaxf(D[idx][2] + b0, 0.f), x3 = fmaxf(D[idx][3] + b1, 0.f);
            if (SK) {
                float s0 = bs[c0], s1 = bs[c0 + 1];
                x0 += fmaxf(S[idx][0] + s0, 0.f); x1 += fmaxf(S[idx][1] + s1, 0.f);
                x2 += fmaxf(S[idx][2] + s0, 0.f); x3 += fmaxf(S[idx][3] + s1, 0.f);
            }
            __half2 h0 = __floats2half2_rn(x0, x1);
            __half2 h1 = __floats2half2_rn(x2, x3);
            int off = c0 * 2;
            *(uint32_t*)(sm + X_HI + rowA + off) = *(uint32_t*)&h0;
            *(uint32_t*)(sm + X_HI + rowB + off) = *(uint32_t*)&h1;
        }
    }
}

// ---------------- main decoder kernel ----------------
__global__ void __launch_bounds__(NTHR, 2)
decoder_kernel(const float* __restrict__ coords,
               const float* __restrict__ b_in,
               const float* __restrict__ b_skip,
               const float* __restrict__ b_before,
               const float* __restrict__ b_after,
               const float* __restrict__ b_out,
               float* __restrict__ out) {
    extern __shared__ unsigned char sm[];
    const uint32_t sb = smem_u32(sm);
    const int tid  = threadIdx.x;
    const int lane = tid & 31;
    const int warp = tid >> 5;
    const int mt   = warp & 1;      // m-half (32 rows)
    const int ng   = warp >> 1;     // n-group (32 neurons)
    const int base = blockIdx.x * NP;

    float* bS = (float*)(sm + SM_BIAS);
    float* cS = (float*)(sm + SM_COORD);

    // prefetch first two weight slots (overlaps with gather)
    cpa_stage(sb + W_A, g_wp + 0 * WPLANE, WPLANE, tid); CPA_COMMIT();   // w_in
    cpa_stage(sb + W_B, g_wp + 1 * WPLANE, WPLANE, tid); CPA_COMMIT();   // w_skip

    // coords + biases
    for (int i = tid; i < NP * 3; i += NTHR) cS[i] = coords[base * 3 + i];
    for (int i = tid; i < 772; i += NTHR) {
        float v;
        if (i < 128)      v = b_in[i];
        else if (i < 256) v = b_skip[i - 128];
        else if (i < 512) v = b_before[i - 256];
        else if (i < 768) v = b_after[i - 512];
        else              v = b_out[i - 768];
        bS[i] = v;
    }
    // zero H pad cols 68..79: 64 rows x 12 cols, 4 threads/row
    {
        int p = tid >> 2, q = tid & 3;
        #pragma unroll
        for (int j = 0; j < 3; j++) {
            int k = FIN + q * 3 + j;
            *(uint16_t*)(sm + H_HI + (p * HSTR + k) * 2) = 0;
        }
    }
    __syncthreads();

    // ---- gather + freq encode -> H (fp16, stride 88): 4 threads/point ----
    {
        const int p = tid >> 2;
        const int q = tid & 3;
        const float c0 = cS[p * 3 + 0];
        const float c1 = cS[p * 3 + 1];
        const float c2 = cS[p * 3 + 2];
        const float nrm[3] = {(c0 + 1.0f) * 0.5f, (c1 + 1.0f) * 0.5f, (c2 + 1.0f) * 0.5f};

        for (int a = q; a < 18; a += 4) {
            int d = a / 6;
            int k = a - 6 * d;
            float freq = 3.14159265358979f * (float)(1 << k);
            float s, c;
            sincosf(nrm[d] * freq, &s, &c);
            int k1 = d * 12 + k, k2 = d * 12 + 6 + k;
            *(__half*)(sm + H_HI + (p * HSTR + k1) * 2) = __float2half_rn(s);
            *(__half*)(sm + H_HI + (p * HSTR + k2) * 2) = __float2half_rn(c);
        }

        const int b = (base + p) >> 16;
        const float gpx[3] = {c0, c0, c1};
        const float gpy[3] = {c1, c2, c2};
        float acc[8];
        #pragma unroll
        for (int j = 0; j < 8; j++) acc[j] = 0.0f;

        #pragma unroll
        for (int pl = 0; pl < 3; pl++) {
            float ix = (gpx[pl] + 1.0f) * 127.5f;
            float iy = (gpy[pl] + 1.0f) * 127.5f;
            float x0f = floorf(ix), y0f = floorf(iy);
            float fx = ix - x0f, fy = iy - y0f;
            int x0 = min(max((int)x0f, 0), RES - 2);
            int y0 = min(max((int)y0f, 0), RES - 2);
            float w00 = (1.0f - fx) * (1.0f - fy);
            float w10 = fx * (1.0f - fy);
            float w01 = (1.0f - fx) * fy;
            float w11 = fx * fy;
            const float* bp = g_tp + ((size_t)(b * 3 + pl) * (RES * RES) + y0 * RES + x0) * TD + q * 8;
            #pragma unroll
            for (int c = 0; c < 2; c++) {
                float4 v00 = *(const float4*)(bp + c * 4);
                float4 v10 = *(const float4*)(bp + TD + c * 4);
                float4 v01 = *(const float4*)(bp + RES * TD + c * 4);
                float4 v11 = *(const float4*)(bp + RES * TD + TD + c * 4);
                acc[c * 4 + 0] += w00 * v00.x + w10 * v10.x + w01 * v01.x + w11 * v11.x;
                acc[c * 4 + 1] += w00 * v00.y + w10 * v10.y + w01 * v01.y + w11 * v11.y;
                acc[c * 4 + 2] += w00 * v00.z + w10 * v10.z + w01 * v01.z + w11 * v11.z;
                acc[c * 4 + 3] += w00 * v00.w + w10 * v10.w + w01 * v01.w + w11 * v11.w;
            }
        }
        #pragma unroll
        for (int j = 0; j < 8; j++) {
            int k = CD + q * 8 + j;
            *(__half*)(sm + H_HI + (p * HSTR + k) * 2) = __float2half_rn(acc[j]);
        }
    }

    // per-thread fragment addresses (warp = mt x ng tile: rows mt*32..+31, cols ng*32..+31)
    const int rowM = mt * 32 + (lane & 15);
    const uint32_t aX = sb + X_HI + (uint32_t)((rowM * STRIDE + (lane >> 4) * 8) * 2);
    const uint32_t aH = sb + H_HI + (uint32_t)((rowM * HSTR + (lane >> 4) * 8) * 2);
    const uint32_t bOff4 = (uint32_t)(ng * 32 * ROWB) +
        (uint32_t)((((lane & 7) + (lane >> 4) * 8) * STRIDE + ((lane >> 3) & 1) * 8) * 2);
    const uint32_t bA4 = sb + W_A + bOff4, bB4 = sb + W_B + bOff4;
    // L6: warps 0..3 handle rows warp*16..+15
    const uint32_t aX6 = sb + X_HI + (uint32_t)(((warp * 16 + (lane & 15)) * STRIDE + (lane >> 4) * 8) * 2);
    const uint32_t bA2 = sb + W_A +
        (uint32_t)(((lane & 7) * STRIDE + ((lane >> 3) & 1) * 8) * 2);

    const int g    = lane >> 2;
    const int tig  = lane & 3;
    const int pBase = mt * 32 + g;
    const int colb  = ng * 32;

    float D[8][4];
    float S[8][4];

    // L1: D = Win h  (W_A)
    CPA_WAIT1();                       // w_in arrived
    __syncthreads();
    mma_layer<5, 16 * HROWB>(aH, bA4, D);
    __syncthreads();                   // all done reading W_A
    cpa_stage(sb + W_A, g_wp + 2 * WPLANE, WPLANE, tid); CPA_COMMIT();   // w_b0 -> W_A
    CPA_WAIT1();                       // w_skip arrived
    __syncthreads();

    // skip: S = Wskip h  (W_B; H still live)
    mma_layer<5, 16 * HROWB>(aH, bB4, S);
    __syncthreads();                   // all done reading W_B + H
    cpa_stage(sb + W_B, g_wp + 3 * WPLANE, WPLANE, tid); CPA_COMMIT();   // w_b1 -> W_B
    epi<false>(sm, D, S, bS + 0, nullptr, pBase, tig, colb);             // x1 -> X (H dead)
    CPA_WAIT1();                       // w_b0 arrived
    __syncthreads();

    // L2: D = W0 x1  (W_A)
    mma_layer<8, 16 * ROWB>(aX, bA4, D);
    __syncthreads();
    cpa_stage(sb + W_A, g_wp + 4 * WPLANE, WPLANE, tid); CPA_COMMIT();   // w_a0 -> W_A
    epi<false>(sm, D, S, bS + 256, nullptr, pBase, tig, colb);           // x2 -> X
    CPA_WAIT1();                       // w_b1 arrived
    __syncthreads();

    // L3: D = W1 x2  (W_B); combine with skip S
    mma_layer<8, 16 * ROWB>(aX, bB4, D);
    __syncthreads();
    cpa_stage(sb + W_B, g_wp + 5 * WPLANE, WPLANE, tid); CPA_COMMIT();   // w_a1 -> W_B
    epi<true>(sm, D, S, bS + 384, bS + 128, pBase, tig, colb);           // x4 -> X
    CPA_WAIT1();                       // w_a0 arrived
    __syncthreads();

    // L4: D = W2 x4  (W_A)
    mma_layer<8, 16 * ROWB>(aX, bA4, D);
    __syncthreads();
    cpa_stage(sb + W_A, g_wp + 6 * WPLANE, 8 * ROWB, tid); CPA_COMMIT(); // w_out -> W_A
    epi<false>(sm, D, S, bS + 512, nullptr, pBase, tig, colb);           // x5 -> X
    CPA_WAIT1();                       // w_a1 arrived
    __syncthreads();

    // L5: D = W3 x5  (W_B)
    mma_layer<8, 16 * ROWB>(aX, bB4, D);
    __syncthreads();
    epi<false>(sm, D, S, bS + 640, nullptr, pBase, tig, colb);           // x6 -> X
    CPA_WAIT0();                       // w_out arrived
    __syncthreads();

    // L6: out = Wout x6 (warps 0..3, rows warp*16..+15; cols 0..3 valid)
    if (warp < 4) {
        float Do[4];
        mma_layer1<8>(aX6, bA2, Do);
        const int pA  = warp * 16 + g;
        const int pB  = pA + 8;
        const int gpA = base + pA, gpB = base + pB;
        if (tig == 0) {
            float v0 = Do[0] + bS[768], v1 = Do[1] + bS[769];
            float v2 = Do[2] + bS[768], v3 = Do[3] + bS[769];
            out[gpA * 3 + 0] = 1.0f / (1.0f + expf(-v0));
            out[gpA * 3 + 1] = 1.0f / (1.0f + expf(-v1));
            out[gpB * 3 + 0] = 1.0f / (1.0f + expf(-v2));
            out[gpB * 3 + 1] = 1.0f / (1.0f + expf(-v3));
        } else if (tig == 1) {
            float v0 = Do[0] + bS[770], v1 = Do[1] + bS[771];
            float v2 = Do[2] + bS[770], v3 = Do[3] + bS[771];
            out[gpA * 3 + 2] = 1.0f / (1.0f + expf(-v0));
            out[gpB * 3 + 2] = 1.0f / (1.0f + expf(-v2));
            float a0 = cS[pA * 3 + 0], a1 = cS[pA * 3 + 1], a2 = cS[pA * 3 + 2];
            bool selA = (a0 > -1.0f) && (a0 < 1.0f) && (a1 > -1.0f) && (a1 < 1.0f) &&
                        (a2 > -1.0f) && (a2 < 1.0f);
            float b0 = cS[pB * 3 + 0], b1 = cS[pB * 3 + 1], b2 = cS[pB * 3 + 2];
            bool selB = (b0 > -1.0f) && (b0 < 1.0f) && (b1 > -1.0f) && (b1 < 1.0f) &&
                        (b2 > -1.0f) && (b2 < 1.0f);
            out[3 * NPTS + gpA] = selA ? expf(v1 - 1.0f) : 0.0f;
            out[3 * NPTS + gpB] = selB ? expf(v3 - 1.0f) : 0.0f;
        }
    }
}

// ---------------- launch ----------------
extern "C" void kernel_launch(void* const* d_in, const int* in_sizes, int n_in,
                              void* d_out, int out_size) {
    const float* triplane = (const float*)d_in[0];
    const float* coords   = (const float*)d_in[1];
    const float* w_in     = (const float*)d_in[2];
    const float* b_in     = (const float*)d_in[3];
    const float* w_skip   = (const float*)d_in[4];
    const float* b_skip   = (const float*)d_in[5];
    const float* w_before = (const float*)d_in[6];
    const float* b_before = (const float*)d_in[7];
    const float* w_after  = (const float*)d_in[8];
    const float* b_after  = (const float*)d_in[9];
    const float* w_out    = (const float*)d_in[10];
    const float* b_out    = (const float*)d_in[11];
    float* out = (float*)d_out;

    static bool attr_set = false;
    if (!attr_set) {
        cudaFuncSetAttribute(decoder_kernel,
                             cudaFuncAttributeMaxDynamicSharedMemorySize, SMEM_BYTES);
        attr_set = true;
    }

    const int wp_blks = (WP_TOT + 255) / 256;
    prep_all_kernel<<<TP_BLKS + wp_blks, 256>>>(
        triplane, w_in, w_skip, w_before, w_after, w_out);
    decoder_kernel<<<NPTS / NP, NTHR, SMEM_BYTES>>>(
        coords, b_in, b_skip, b_before, b_after, b_out, out);
}